// round 12
// baseline (speedup 1.0000x reference)
#include <cuda_runtime.h>
#include <cuda_bf16.h>
#include <cuda_fp8.h>
#include <stdint.h>
#include <stddef.h>
#include <math.h>

#define BATCH 8
#define NN 2048
#define DD 768
#define NTILE 16
#define NPAIRS (NTILE * (NTILE + 1) / 2)   // 136 upper-triangle tiles

// ---------------- device scratch (allocation-free rule) ----------------
__device__ __nv_bfloat16 g_midn[(size_t)BATCH * NN * DD];   // normalized mid (bf16)
__device__ unsigned char g_ftp8[(size_t)BATCH * DD * NN];   // final^T (e4m3), [d][n]
__device__ unsigned char g_expb[(size_t)BATCH * NN * NN];   // e4m3 exp(sim)
__device__ unsigned      g_confbits[BATCH * NN];            // ordered-uint row max
__device__ float         g_conf[BATCH * NN];                // row max (confidence)
__device__ float         g_rinv[BATCH * NN];                // 1 / row sum of exp

__device__ __forceinline__ uint32_t s2u(const void* p) {
    return (uint32_t)__cvta_generic_to_shared(p);
}
__device__ __forceinline__ void cpa16(void* dst, const void* src) {
    asm volatile("cp.async.cg.shared.global [%0], [%1], 16;"
                 :: "r"(s2u(dst)), "l"(src));
}
#define CP_COMMIT() asm volatile("cp.async.commit_group;")
#define CP_WAIT(n)  asm volatile("cp.async.wait_group %0;" :: "n"(n))

// monotonic float<->uint for atomicMax
__device__ __forceinline__ unsigned fenc(float x) {
    unsigned b = __float_as_uint(x);
    return (b & 0x80000000u) ? ~b : (b | 0x80000000u);
}
__device__ __forceinline__ float fdec(unsigned e) {
    unsigned b = (e & 0x80000000u) ? (e ^ 0x80000000u) : ~e;
    return __uint_as_float(b);
}
__device__ __forceinline__ uint32_t pk2f8(float a, float b2) {
    return (uint32_t)__nv_cvt_float2_to_fp8x2(make_float2(a, b2),
                                              __NV_SATFINITE, __NV_E4M3);
}
__device__ __forceinline__ uint32_t pk4f8(float a, float b2, float c, float d) {
    return pk2f8(a, b2) | (pk2f8(c, d) << 16);
}
__device__ __forceinline__ float2 up2f8(uint16_t x) {
    __half2_raw hr = __nv_cvt_fp8x2_to_halfraw2((__nv_fp8x2_storage_t)x, __NV_E4M3);
    return __half22float2(*(__half2*)&hr);
}

// swizzled index (halves) for bf16 tiles: 128 rows x 32 halves (64B rows)
__device__ __forceinline__ int swA(int row, int kh) {
    return (row << 5) | ((((kh >> 3) ^ ((row >> 1) & 3)) << 3));
}
// swizzled byte offset for fp8 tiles: 128 rows x 64 bytes, 16B chunks
__device__ __forceinline__ int off8(int r, int c16) {
    return (r << 6) | ((((c16) ^ ((r >> 1) & 3)) & 3) << 4);
}

// ---------------------------------------------------------------------------
// Kernel 1: L2-normalize mid along D -> bf16; reset g_confbits.
// ---------------------------------------------------------------------------
__global__ void norm_kernel(const float* __restrict__ mid) {
    const int row = blockIdx.x;
    if (threadIdx.x == 0) g_confbits[row] = fenc(-INFINITY);
    const float* x = mid + (size_t)row * DD;
    __nv_bfloat16* y = g_midn + (size_t)row * DD;

    float s = 0.f;
    for (int i = threadIdx.x; i < DD; i += blockDim.x) {
        float v = x[i];
        s += v * v;
    }
    __shared__ float sh[32];
    #pragma unroll
    for (int o = 16; o > 0; o >>= 1) s += __shfl_xor_sync(0xffffffffu, s, o);
    const int w = threadIdx.x >> 5, l = threadIdx.x & 31;
    if (l == 0) sh[w] = s;
    __syncthreads();
    if (w == 0) {
        float v = (threadIdx.x < (blockDim.x >> 5)) ? sh[threadIdx.x] : 0.f;
        #pragma unroll
        for (int o = 16; o > 0; o >>= 1) v += __shfl_xor_sync(0xffffffffu, v, o);
        if (threadIdx.x == 0) sh[0] = v;
    }
    __syncthreads();
    const float inv = 1.0f / fmaxf(sqrtf(sh[0]), 1e-12f);
    for (int i = threadIdx.x; i < DD; i += blockDim.x)
        y[i] = __float2bfloat16(x[i] * inv);
}

// ---------------------------------------------------------------------------
// Kernel 1b: transpose final fp32 [n][d] -> e4m3 [d][n].
// ---------------------------------------------------------------------------
__global__ void transpose_fp8(const float* __restrict__ fin) {
    __shared__ float t[32][33];
    const int b = blockIdx.z;
    const int d0 = blockIdx.x * 32, n0 = blockIdx.y * 32;
    const float* F = fin + (size_t)b * NN * DD;
    unsigned char* T = g_ftp8 + (size_t)b * DD * NN;
    const int x = threadIdx.x, y = threadIdx.y;
    #pragma unroll
    for (int i = 0; i < 4; i++)
        t[y + 8 * i][x] = F[(size_t)(n0 + y + 8 * i) * DD + d0 + x];
    __syncthreads();
    uint32_t word = pk4f8(t[y * 4 + 0][x], t[y * 4 + 1][x],
                          t[y * 4 + 2][x], t[y * 4 + 3][x]);
    *(uint32_t*)(T + (size_t)(d0 + x) * NN + n0 + y * 4) = word;
}

// ---------------------------------------------------------------------------
// Kernel 2: sim GEMM (upper-triangle tiles, bf16 HMMA). 128x128 CTA tile,
// 4 warps (64x64 warp tile), k-chunk 32 halves, 4-stage pipeline.
// Diag tiles skip B load (A==B). Epilogue: exp(sim) e4m3 + row-max atomics.
// ---------------------------------------------------------------------------
#define KT_SIM (DD / 32)                   // 24 iterations
#define STG    4096                        // halves per stage tile (128x32)
#define SIM_SMEM (128 * 129 * 4)           // 66048 B (>= 8 stage-tiles * 8KB = 65536)

__global__ __launch_bounds__(128) void sim_mma() {
    extern __shared__ char dsm[];
    __nv_bfloat16* As = (__nv_bfloat16*)dsm;          // [4][STG]
    __nv_bfloat16* Bs = As + 4 * STG;                 // [4][STG]
    float* T = (float*)dsm;                           // [128][129], reused

    int t = blockIdx.x, bi = 0, rem = NTILE;
    while (t >= rem) { t -= rem; rem--; bi++; }
    const int bj = bi + t;
    const int b = blockIdx.z;
    const int row0 = bi << 7, col0 = bj << 7;
    const bool diag = (bi == bj);
    const __nv_bfloat16* Ab = g_midn + (size_t)b * NN * DD;
    const __nv_bfloat16* Bbase = diag ? As : Bs;      // diag: B operand = A tile

    const int tid = threadIdx.x, lane = tid & 31, wid = tid >> 5;
    const int wm = (wid >> 1) << 6;    // 0, 64
    const int wn = (wid & 1) << 6;     // 0, 64

    float acc[4][8][4];
    #pragma unroll
    for (int i = 0; i < 4; i++)
        #pragma unroll
        for (int j = 0; j < 8; j++)
            #pragma unroll
            for (int k = 0; k < 4; k++) acc[i][j][k] = 0.f;

    // loader: 512 16B-chunks per tile, 4 per thread per operand
    #define SIM_LOAD(kt, p)                                                     \
        do {                                                                    \
            _Pragma("unroll")                                                   \
            for (int q = 0; q < 4; q++) {                                       \
                int ch = tid + 128 * q;                                         \
                int r = ch >> 2, c = ch & 3;                                    \
                int so = (r << 5) | (((c ^ ((r >> 1) & 3))) << 3);              \
                cpa16(&As[(p) * STG + so],                                      \
                      Ab + (size_t)(row0 + r) * DD + (kt) + c * 8);             \
                if (!diag)                                                      \
                    cpa16(&Bs[(p) * STG + so],                                  \
                          Ab + (size_t)(col0 + r) * DD + (kt) + c * 8);         \
            }                                                                   \
        } while (0)

    SIM_LOAD(0, 0);
    CP_COMMIT();
    SIM_LOAD(32, 1);
    CP_COMMIT();
    SIM_LOAD(64, 2);
    CP_COMMIT();

    int p = 0, pw = 3;
    for (int kti = 0; kti < KT_SIM; kti++) {
        CP_WAIT(2);
        __syncthreads();
        if (kti + 3 < KT_SIM) SIM_LOAD((kti + 3) * 32, pw);
        CP_COMMIT();

        #pragma unroll
        for (int ks = 0; ks < 2; ks++) {
            uint32_t af[4][4];
            #pragma unroll
            for (int i = 0; i < 4; i++) {
                int row = wm + i * 16 + (lane & 15);
                int kh  = ks * 16 + ((lane >> 4) << 3);
                uint32_t ad = s2u(&As[p * STG + swA(row, kh)]);
                asm volatile("ldmatrix.sync.aligned.m8n8.x4.shared.b16 {%0,%1,%2,%3}, [%4];"
                    : "=r"(af[i][0]), "=r"(af[i][1]), "=r"(af[i][2]), "=r"(af[i][3])
                    : "r"(ad));
            }
            uint32_t bf[8][2];
            #pragma unroll
            for (int j2 = 0; j2 < 4; j2++) {
                int row = wn + j2 * 16 + (lane & 7) + (((lane >> 4) & 1) << 3);
                int kh  = ks * 16 + (((lane >> 3) & 1) << 3);
                uint32_t bd = s2u(&Bbase[p * STG + swA(row, kh)]);
                asm volatile("ldmatrix.sync.aligned.m8n8.x4.shared.b16 {%0,%1,%2,%3}, [%4];"
                    : "=r"(bf[j2 * 2][0]), "=r"(bf[j2 * 2][1]),
                      "=r"(bf[j2 * 2 + 1][0]), "=r"(bf[j2 * 2 + 1][1])
                    : "r"(bd));
            }
            #pragma unroll
            for (int i = 0; i < 4; i++)
                #pragma unroll
                for (int j = 0; j < 8; j++)
                    asm volatile(
                        "mma.sync.aligned.m16n8k16.row.col.f32.bf16.bf16.f32 "
                        "{%0,%1,%2,%3}, {%4,%5,%6,%7}, {%8,%9}, {%0,%1,%2,%3};"
                        : "+f"(acc[i][j][0]), "+f"(acc[i][j][1]),
                          "+f"(acc[i][j][2]), "+f"(acc[i][j][3])
                        : "r"(af[i][0]), "r"(af[i][1]), "r"(af[i][2]), "r"(af[i][3]),
                          "r"(bf[j][0]), "r"(bf[j][1]));
        }
        p = (p + 1) & 3;
        pw = (pw + 1) & 3;
    }
    __syncthreads();   // all warps done reading stages before T overwrites them

    // ---- stage fp32 tile (diag zeroed) in SMEM ----
    const int gr = lane >> 2, gc = (lane & 3) << 1;
    #pragma unroll
    for (int i = 0; i < 4; i++) {
        const int rl = wm + i * 16 + gr;
        #pragma unroll
        for (int j = 0; j < 8; j++) {
            const int cl = wn + j * 8 + gc;
            const int gofs = (row0 + rl) - (col0 + cl);
            T[rl * 129 + cl]           = (gofs == 0)  ? 0.f : acc[i][j][0];
            T[rl * 129 + cl + 1]       = (gofs == 1)  ? 0.f : acc[i][j][1];
            T[(rl + 8) * 129 + cl]     = (gofs == -8) ? 0.f : acc[i][j][2];
            T[(rl + 8) * 129 + cl + 1] = (gofs == -7) ? 0.f : acc[i][j][3];
        }
    }
    __syncthreads();

    // ---- row pass: write exp(tile) as e4m3 + row-max atomics ----
    {
        const int rr = tid;                 // one row per thread
        float mx = -INFINITY;
        uint32_t* dst = (uint32_t*)(g_expb + (size_t)b * NN * NN
                                    + (size_t)(row0 + rr) * NN + col0);
        #pragma unroll
        for (int c = 0; c < 128; c += 4) {
            float v0 = T[rr * 129 + c + 0];
            float v1 = T[rr * 129 + c + 1];
            float v2 = T[rr * 129 + c + 2];
            float v3 = T[rr * 129 + c + 3];
            mx = fmaxf(mx, fmaxf(fmaxf(v0, v1), fmaxf(v2, v3)));
            dst[c >> 2] = pk4f8(__expf(v0), __expf(v1), __expf(v2), __expf(v3));
        }
        atomicMax(&g_confbits[b * NN + row0 + rr], fenc(mx));
    }

    // ---- col pass (mirror) for off-diagonal tiles ----
    if (!diag) {
        const int cc = tid;                 // one column per thread
        float mx = -INFINITY;
        uint32_t* dst = (uint32_t*)(g_expb + (size_t)b * NN * NN
                                    + (size_t)(col0 + cc) * NN + row0);
        #pragma unroll
        for (int r = 0; r < 128; r += 4) {
            float v0 = T[(r + 0) * 129 + cc];
            float v1 = T[(r + 1) * 129 + cc];
            float v2 = T[(r + 2) * 129 + cc];
            float v3 = T[(r + 3) * 129 + cc];
            mx = fmaxf(mx, fmaxf(fmaxf(v0, v1), fmaxf(v2, v3)));
            dst[r >> 2] = pk4f8(__expf(v0), __expf(v1), __expf(v2), __expf(v3));
        }
        atomicMax(&g_confbits[b * NN + col0 + cc], fenc(mx));
    }
}

// ---------------------------------------------------------------------------
// Kernel 3: row sums of e4m3 exp -> rinv; 2 rows per block (MLP 2/thread).
// ---------------------------------------------------------------------------
__global__ void rowsum_kernel() {
    const int rbase = blockIdx.x * 2;
    const int half = threadIdx.x >> 6;            // 0/1 -> row within pair
    const int t = threadIdx.x & 63;
    const int row = rbase + half;
    const uint4* p = (const uint4*)(g_expb + (size_t)row * NN) + t * 2;
    uint4 v1 = p[0];
    uint4 v2 = p[1];
    float s = 0.f;
    {
        const uint32_t w4[8] = {v1.x, v1.y, v1.z, v1.w, v2.x, v2.y, v2.z, v2.w};
        #pragma unroll
        for (int h = 0; h < 8; h++) {
            float2 a = up2f8((uint16_t)(w4[h] & 0xFFFF));
            float2 b2 = up2f8((uint16_t)(w4[h] >> 16));
            s += (a.x + a.y) + (b2.x + b2.y);
        }
    }
    __shared__ float sh[4];
    #pragma unroll
    for (int o = 16; o > 0; o >>= 1) s += __shfl_xor_sync(0xffffffffu, s, o);
    const int w = threadIdx.x >> 5, l = threadIdx.x & 31;
    if (l == 0) sh[w] = s;
    __syncthreads();
    if ((threadIdx.x & 63) == 0) {
        float v = sh[half * 2] + sh[half * 2 + 1];
        g_conf[row] = fdec(g_confbits[row]);
        g_rinv[row] = 1.0f / v;
    }
}

// ---------------------------------------------------------------------------
// Kernel 4: refined = (E @ F) * rinv ; out = cw*refined + (1-cw)*final.
// fp8 e4m3 QMMA m16n8k32. 128x128 CTA tile, 4 warps (64x64 warp tile),
// k-chunk 64 bytes, 4-stage pipeline.
// ---------------------------------------------------------------------------
#define KT_OUT (NN / 64)                   // 32 iterations
#define STG8   8192                        // bytes per stage tile (128x64)
#define OUT_SMEM (8 * STG8)                // 65536

__global__ __launch_bounds__(128) void out_mma(const float* __restrict__ fin,
                                               float* __restrict__ out) {
    extern __shared__ char dsm[];
    unsigned char* Es = (unsigned char*)dsm;          // [4][STG8]
    unsigned char* Fs = Es + 4 * STG8;                // [4][STG8]
    const int b = blockIdx.z;
    const int row0 = blockIdx.y << 7;   // n rows
    const int col0 = blockIdx.x << 7;   // d cols
    const unsigned char* Eb = g_expb + (size_t)b * NN * NN;
    const unsigned char* Tb = g_ftp8 + (size_t)b * DD * NN;

    const int tid = threadIdx.x, lane = tid & 31, wid = tid >> 5;
    const int wm = (wid >> 1) << 6;
    const int wn = (wid & 1) << 6;

    float acc[4][8][4];
    #pragma unroll
    for (int i = 0; i < 4; i++)
        #pragma unroll
        for (int j = 0; j < 8; j++)
            #pragma unroll
            for (int k = 0; k < 4; k++) acc[i][j][k] = 0.f;

    // loader: 512 16B-chunks per tile, 4 per thread per operand
    #define OUT_LOAD(kt, p)                                                     \
        do {                                                                    \
            _Pragma("unroll")                                                   \
            for (int q = 0; q < 4; q++) {                                       \
                int ch = tid + 128 * q;                                         \
                int r = ch >> 2, c = ch & 3;                                    \
                int so = off8(r, c);                                            \
                cpa16(&Es[(p) * STG8 + so],                                     \
                      Eb + (size_t)(row0 + r) * NN + (kt) + c * 16);            \
                cpa16(&Fs[(p) * STG8 + so],                                     \
                      Tb + (size_t)(col0 + r) * NN + (kt) + c * 16);            \
            }                                                                   \
        } while (0)

    OUT_LOAD(0, 0);
    CP_COMMIT();
    OUT_LOAD(64, 1);
    CP_COMMIT();
    OUT_LOAD(128, 2);
    CP_COMMIT();

    int p = 0, pw = 3;
    for (int kti = 0; kti < KT_OUT; kti++) {
        CP_WAIT(2);
        __syncthreads();
        if (kti + 3 < KT_OUT) OUT_LOAD((kti + 3) * 64, pw);
        CP_COMMIT();

        #pragma unroll
        for (int ks = 0; ks < 2; ks++) {
            uint32_t af[4][4];
            #pragma unroll
            for (int i = 0; i < 4; i++) {
                int row = wm + i * 16 + (lane & 15);
                int c16 = ks * 2 + (lane >> 4);
                uint32_t ad = s2u(&Es[p * STG8 + off8(row, c16)]);
                asm volatile("ldmatrix.sync.aligned.m8n8.x4.shared.b16 {%0,%1,%2,%3}, [%4];"
                    : "=r"(af[i][0]), "=r"(af[i][1]), "=r"(af[i][2]), "=r"(af[i][3])
                    : "r"(ad));
            }
            uint32_t bf[8][2];
            #pragma unroll
            for (int j2 = 0; j2 < 4; j2++) {
                int row = wn + j2 * 16 + (lane & 7) + (((lane >> 4) & 1) << 3);
                int c16 = ks * 2 + ((lane >> 3) & 1);
                uint32_t bd = s2u(&Fs[p * STG8 + off8(row, c16)]);
                asm volatile("ldmatrix.sync.aligned.m8n8.x4.shared.b16 {%0,%1,%2,%3}, [%4];"
                    : "=r"(bf[j2 * 2][0]), "=r"(bf[j2 * 2][1]),
                      "=r"(bf[j2 * 2 + 1][0]), "=r"(bf[j2 * 2 + 1][1])
                    : "r"(bd));
            }
            #pragma unroll
            for (int i = 0; i < 4; i++)
                #pragma unroll
                for (int j = 0; j < 8; j++)
                    asm volatile(
                        "mma.sync.aligned.m16n8k32.row.col.f32.e4m3.e4m3.f32 "
                        "{%0,%1,%2,%3}, {%4,%5,%6,%7}, {%8,%9}, {%0,%1,%2,%3};"
                        : "+f"(acc[i][j][0]), "+f"(acc[i][j][1]),
                          "+f"(acc[i][j][2]), "+f"(acc[i][j][3])
                        : "r"(af[i][0]), "r"(af[i][1]), "r"(af[i][2]), "r"(af[i][3]),
                          "r"(bf[j][0]), "r"(bf[j][1]));
        }
        p = (p + 1) & 3;
        pw = (pw + 1) & 3;
    }

    const float* F32 = fin + (size_t)b * NN * DD;
    float* O = out + (size_t)b * NN * DD;
    const int gr = lane >> 2, gc = (lane & 3) << 1;
    #pragma unroll
    for (int i = 0; i < 4; i++) {
        #pragma unroll
        for (int half = 0; half < 2; half++) {
            int r = row0 + wm + i * 16 + gr + half * 8;
            const float cw  = g_conf[b * NN + r];
            const float inv = g_rinv[b * NN + r];
            #pragma unroll
            for (int j = 0; j < 8; j++) {
                int c = col0 + wn + j * 8 + gc;
                float2 f = *(const float2*)(F32 + (size_t)r * DD + c);
                float2 o;
                o.x = cw * (acc[i][j][half * 2 + 0] * inv) + (1.0f - cw) * f.x;
                o.y = cw * (acc[i][j][half * 2 + 1] * inv) + (1.0f - cw) * f.y;
                *(float2*)(O + (size_t)r * DD + c) = o;
            }
        }
    }
}

// ---------------------------------------------------------------------------
extern "C" void kernel_launch(void* const* d_in, const int* in_sizes, int n_in,
                              void* d_out, int out_size) {
    const float* final_f = (const float*)d_in[0];
    const float* mid_f   = (const float*)d_in[1];
    float* out = (float*)d_out;

    static int configured = 0;
    if (!configured) {
        cudaFuncSetAttribute(sim_mma, cudaFuncAttributeMaxDynamicSharedMemorySize,
                             SIM_SMEM);
        cudaFuncSetAttribute(out_mma, cudaFuncAttributeMaxDynamicSharedMemorySize,
                             OUT_SMEM);
        configured = 1;
    }

    norm_kernel<<<BATCH * NN, 256>>>(mid_f);
    transpose_fp8<<<dim3(DD / 32, NN / 32, BATCH), dim3(32, 8)>>>(final_f);

    sim_mma<<<dim3(NPAIRS, 1, BATCH), 128, SIM_SMEM>>>();

    rowsum_kernel<<<BATCH * NN / 2, 128>>>();

    out_mma<<<dim3(DD / 128, NN / 128, BATCH), 128, OUT_SMEM>>>(final_f, out);
}

// round 13
// speedup vs baseline: 1.0437x; 1.0437x over previous
#include <cuda_runtime.h>
#include <cuda_bf16.h>
#include <cuda_fp8.h>
#include <stdint.h>
#include <stddef.h>
#include <math.h>

#define BATCH 8
#define NN 2048
#define DD 768
#define NTILE 16
#define NPAIRS (NTILE * (NTILE + 1) / 2)   // 136 upper-triangle tiles

// ---------------- device scratch (allocation-free rule) ----------------
__device__ __nv_bfloat16 g_midn[(size_t)BATCH * NN * DD];   // normalized mid (bf16)
__device__ unsigned char g_ftp8[(size_t)BATCH * DD * NN];   // final^T (e4m3), [d][n]
__device__ unsigned char g_expb[(size_t)BATCH * NN * NN];   // e4m3 exp(sim)
__device__ unsigned      g_confbits[BATCH * NN];            // ordered-uint row max
__device__ float         g_conf[BATCH * NN];                // row max (confidence)
__device__ float         g_rinv[BATCH * NN];                // 1 / row sum of exp

__device__ __forceinline__ uint32_t s2u(const void* p) {
    return (uint32_t)__cvta_generic_to_shared(p);
}
__device__ __forceinline__ void cpa16(void* dst, const void* src) {
    asm volatile("cp.async.cg.shared.global [%0], [%1], 16;"
                 :: "r"(s2u(dst)), "l"(src));
}
#define CP_COMMIT() asm volatile("cp.async.commit_group;")
#define CP_WAIT(n)  asm volatile("cp.async.wait_group %0;" :: "n"(n))

// monotonic float<->uint for atomicMax
__device__ __forceinline__ unsigned fenc(float x) {
    unsigned b = __float_as_uint(x);
    return (b & 0x80000000u) ? ~b : (b | 0x80000000u);
}
__device__ __forceinline__ float fdec(unsigned e) {
    unsigned b = (e & 0x80000000u) ? (e ^ 0x80000000u) : ~e;
    return __uint_as_float(b);
}
__device__ __forceinline__ uint32_t pk2f8(float a, float b2) {
    return (uint32_t)__nv_cvt_float2_to_fp8x2(make_float2(a, b2),
                                              __NV_SATFINITE, __NV_E4M3);
}
__device__ __forceinline__ uint32_t pk4f8(float a, float b2, float c, float d) {
    return pk2f8(a, b2) | (pk2f8(c, d) << 16);
}
__device__ __forceinline__ float2 up2f8(uint16_t x) {
    __half2_raw hr = __nv_cvt_fp8x2_to_halfraw2((__nv_fp8x2_storage_t)x, __NV_E4M3);
    return __half22float2(*(__half2*)&hr);
}

// swizzled index (halves) for bf16 tiles: 128 rows x 32 halves (64B rows)
__device__ __forceinline__ int swA(int row, int kh) {
    return (row << 5) | ((((kh >> 3) ^ ((row >> 1) & 3)) << 3));
}
// swizzled byte offset for fp8 tiles with 128B rows (8 x 16B chunks)
__device__ __forceinline__ int off8w(int r, int c16) {
    return (r << 7) | ((((c16) ^ (r & 7)) & 7) << 4);
}

// ---------------------------------------------------------------------------
// Kernel 1: L2-normalize mid along D -> bf16; reset g_confbits.
// ---------------------------------------------------------------------------
__global__ void norm_kernel(const float* __restrict__ mid) {
    const int row = blockIdx.x;
    if (threadIdx.x == 0) g_confbits[row] = fenc(-INFINITY);
    const float* x = mid + (size_t)row * DD;
    __nv_bfloat16* y = g_midn + (size_t)row * DD;

    float s = 0.f;
    for (int i = threadIdx.x; i < DD; i += blockDim.x) {
        float v = x[i];
        s += v * v;
    }
    __shared__ float sh[32];
    #pragma unroll
    for (int o = 16; o > 0; o >>= 1) s += __shfl_xor_sync(0xffffffffu, s, o);
    const int w = threadIdx.x >> 5, l = threadIdx.x & 31;
    if (l == 0) sh[w] = s;
    __syncthreads();
    if (w == 0) {
        float v = (threadIdx.x < (blockDim.x >> 5)) ? sh[threadIdx.x] : 0.f;
        #pragma unroll
        for (int o = 16; o > 0; o >>= 1) v += __shfl_xor_sync(0xffffffffu, v, o);
        if (threadIdx.x == 0) sh[0] = v;
    }
    __syncthreads();
    const float inv = 1.0f / fmaxf(sqrtf(sh[0]), 1e-12f);
    for (int i = threadIdx.x; i < DD; i += blockDim.x)
        y[i] = __float2bfloat16(x[i] * inv);
}

// ---------------------------------------------------------------------------
// Kernel 1b: transpose final fp32 [n][d] -> e4m3 [d][n].
// ---------------------------------------------------------------------------
__global__ void transpose_fp8(const float* __restrict__ fin) {
    __shared__ float t[32][33];
    const int b = blockIdx.z;
    const int d0 = blockIdx.x * 32, n0 = blockIdx.y * 32;
    const float* F = fin + (size_t)b * NN * DD;
    unsigned char* T = g_ftp8 + (size_t)b * DD * NN;
    const int x = threadIdx.x, y = threadIdx.y;
    #pragma unroll
    for (int i = 0; i < 4; i++)
        t[y + 8 * i][x] = F[(size_t)(n0 + y + 8 * i) * DD + d0 + x];
    __syncthreads();
    uint32_t word = pk4f8(t[y * 4 + 0][x], t[y * 4 + 1][x],
                          t[y * 4 + 2][x], t[y * 4 + 3][x]);
    *(uint32_t*)(T + (size_t)(d0 + x) * NN + n0 + y * 4) = word;
}

// ---------------------------------------------------------------------------
// Kernel 2: sim GEMM (upper-triangle tiles, bf16 HMMA). 128x128 CTA tile,
// 4 warps (64x64 warp tile), k-chunk 32 halves, 4-stage pipeline,
// fragment double-buffering. Epilogue: exp(sim) e4m3 + row-max atomics.
// ---------------------------------------------------------------------------
#define KT_SIM (DD / 32)                   // 24 iterations
#define STG    4096                        // halves per stage tile (128x32)
#define SIM_SMEM (128 * 129 * 4)           // 66048 B (>= 8 stage-tiles * 8KB)

__global__ __launch_bounds__(128, 2) void sim_mma() {
    extern __shared__ char dsm[];
    __nv_bfloat16* As = (__nv_bfloat16*)dsm;          // [4][STG]
    __nv_bfloat16* Bs = As + 4 * STG;                 // [4][STG]
    float* T = (float*)dsm;                           // [128][129], reused

    int t = blockIdx.x, bi = 0, rem = NTILE;
    while (t >= rem) { t -= rem; rem--; bi++; }
    const int bj = bi + t;
    const int b = blockIdx.z;
    const int row0 = bi << 7, col0 = bj << 7;
    const bool diag = (bi == bj);
    const __nv_bfloat16* Ab = g_midn + (size_t)b * NN * DD;
    const __nv_bfloat16* Bbase = diag ? As : Bs;      // diag: B operand = A tile

    const int tid = threadIdx.x, lane = tid & 31, wid = tid >> 5;
    const int wm = (wid >> 1) << 6;    // 0, 64
    const int wn = (wid & 1) << 6;     // 0, 64

    float acc[4][8][4];
    #pragma unroll
    for (int i = 0; i < 4; i++)
        #pragma unroll
        for (int j = 0; j < 8; j++)
            #pragma unroll
            for (int k = 0; k < 4; k++) acc[i][j][k] = 0.f;

    #define SIM_LOAD(kt, p_)                                                    \
        do {                                                                    \
            _Pragma("unroll")                                                   \
            for (int q = 0; q < 4; q++) {                                       \
                int ch = tid + 128 * q;                                         \
                int r = ch >> 2, c = ch & 3;                                    \
                int so = (r << 5) | (((c ^ ((r >> 1) & 3))) << 3);              \
                cpa16(&As[(p_) * STG + so],                                     \
                      Ab + (size_t)(row0 + r) * DD + (kt) + c * 8);             \
                if (!diag)                                                      \
                    cpa16(&Bs[(p_) * STG + so],                                 \
                          Ab + (size_t)(col0 + r) * DD + (kt) + c * 8);         \
            }                                                                   \
        } while (0)

    uint32_t af[2][4][4], bf[2][8][2];

    #define SIM_FRAGS(ks, fb)                                                   \
        do {                                                                    \
            _Pragma("unroll")                                                   \
            for (int i = 0; i < 4; i++) {                                       \
                int row = wm + i * 16 + (lane & 15);                            \
                int kh  = (ks) * 16 + ((lane >> 4) << 3);                       \
                uint32_t ad = s2u(&As[p * STG + swA(row, kh)]);                 \
                asm volatile("ldmatrix.sync.aligned.m8n8.x4.shared.b16 {%0,%1,%2,%3}, [%4];" \
                    : "=r"(af[fb][i][0]), "=r"(af[fb][i][1]),                   \
                      "=r"(af[fb][i][2]), "=r"(af[fb][i][3]) : "r"(ad));        \
            }                                                                   \
            _Pragma("unroll")                                                   \
            for (int j2 = 0; j2 < 4; j2++) {                                    \
                int row = wn + j2 * 16 + (lane & 7) + (((lane >> 4) & 1) << 3); \
                int kh  = (ks) * 16 + (((lane >> 3) & 1) << 3);                 \
                uint32_t bd = s2u(&Bbase[p * STG + swA(row, kh)]);              \
                asm volatile("ldmatrix.sync.aligned.m8n8.x4.shared.b16 {%0,%1,%2,%3}, [%4];" \
                    : "=r"(bf[fb][j2 * 2][0]), "=r"(bf[fb][j2 * 2][1]),         \
                      "=r"(bf[fb][j2 * 2 + 1][0]), "=r"(bf[fb][j2 * 2 + 1][1])  \
                    : "r"(bd));                                                 \
            }                                                                   \
        } while (0)

    SIM_LOAD(0, 0);
    CP_COMMIT();
    SIM_LOAD(32, 1);
    CP_COMMIT();
    SIM_LOAD(64, 2);
    CP_COMMIT();

    int p = 0, pw = 3;
    for (int kti = 0; kti < KT_SIM; kti++) {
        CP_WAIT(2);
        __syncthreads();
        if (kti + 3 < KT_SIM) SIM_LOAD((kti + 3) * 32, pw);
        CP_COMMIT();

        SIM_FRAGS(0, 0);
        #pragma unroll
        for (int ks = 0; ks < 2; ks++) {
            if (ks + 1 < 2) SIM_FRAGS(ks + 1, (ks + 1) & 1);
            const int fb = ks & 1;
            #pragma unroll
            for (int i = 0; i < 4; i++)
                #pragma unroll
                for (int j = 0; j < 8; j++)
                    asm volatile(
                        "mma.sync.aligned.m16n8k16.row.col.f32.bf16.bf16.f32 "
                        "{%0,%1,%2,%3}, {%4,%5,%6,%7}, {%8,%9}, {%0,%1,%2,%3};"
                        : "+f"(acc[i][j][0]), "+f"(acc[i][j][1]),
                          "+f"(acc[i][j][2]), "+f"(acc[i][j][3])
                        : "r"(af[fb][i][0]), "r"(af[fb][i][1]),
                          "r"(af[fb][i][2]), "r"(af[fb][i][3]),
                          "r"(bf[fb][j][0]), "r"(bf[fb][j][1]));
        }
        p = (p + 1) & 3;
        pw = (pw + 1) & 3;
    }
    __syncthreads();   // all warps done reading stages before T overwrites them

    // ---- stage fp32 tile (diag zeroed) in SMEM ----
    const int gr = lane >> 2, gc = (lane & 3) << 1;
    #pragma unroll
    for (int i = 0; i < 4; i++) {
        const int rl = wm + i * 16 + gr;
        #pragma unroll
        for (int j = 0; j < 8; j++) {
            const int cl = wn + j * 8 + gc;
            const int gofs = (row0 + rl) - (col0 + cl);
            T[rl * 129 + cl]           = (gofs == 0)  ? 0.f : acc[i][j][0];
            T[rl * 129 + cl + 1]       = (gofs == 1)  ? 0.f : acc[i][j][1];
            T[(rl + 8) * 129 + cl]     = (gofs == -8) ? 0.f : acc[i][j][2];
            T[(rl + 8) * 129 + cl + 1] = (gofs == -7) ? 0.f : acc[i][j][3];
        }
    }
    __syncthreads();

    // ---- row pass: write exp(tile) as e4m3 + row-max atomics ----
    {
        const int rr = tid;                 // one row per thread
        float mx = -INFINITY;
        uint32_t* dst = (uint32_t*)(g_expb + (size_t)b * NN * NN
                                    + (size_t)(row0 + rr) * NN + col0);
        #pragma unroll
        for (int c = 0; c < 128; c += 4) {
            float v0 = T[rr * 129 + c + 0];
            float v1 = T[rr * 129 + c + 1];
            float v2 = T[rr * 129 + c + 2];
            float v3 = T[rr * 129 + c + 3];
            mx = fmaxf(mx, fmaxf(fmaxf(v0, v1), fmaxf(v2, v3)));
            dst[c >> 2] = pk4f8(__expf(v0), __expf(v1), __expf(v2), __expf(v3));
        }
        atomicMax(&g_confbits[b * NN + row0 + rr], fenc(mx));
    }

    // ---- col pass (mirror) for off-diagonal tiles ----
    if (!diag) {
        const int cc = tid;                 // one column per thread
        float mx = -INFINITY;
        uint32_t* dst = (uint32_t*)(g_expb + (size_t)b * NN * NN
                                    + (size_t)(col0 + cc) * NN + row0);
        #pragma unroll
        for (int r = 0; r < 128; r += 4) {
            float v0 = T[(r + 0) * 129 + cc];
            float v1 = T[(r + 1) * 129 + cc];
            float v2 = T[(r + 2) * 129 + cc];
            float v3 = T[(r + 3) * 129 + cc];
            mx = fmaxf(mx, fmaxf(fmaxf(v0, v1), fmaxf(v2, v3)));
            dst[r >> 2] = pk4f8(__expf(v0), __expf(v1), __expf(v2), __expf(v3));
        }
        atomicMax(&g_confbits[b * NN + col0 + cc], fenc(mx));
    }
}

// ---------------------------------------------------------------------------
// Kernel 3: row sums of e4m3 exp -> rinv; 2 rows per block (MLP 2/thread).
// ---------------------------------------------------------------------------
__global__ void rowsum_kernel() {
    const int rbase = blockIdx.x * 2;
    const int half = threadIdx.x >> 6;            // 0/1 -> row within pair
    const int t = threadIdx.x & 63;
    const int row = rbase + half;
    const uint4* p = (const uint4*)(g_expb + (size_t)row * NN) + t * 2;
    uint4 v1 = p[0];
    uint4 v2 = p[1];
    float s = 0.f;
    {
        const uint32_t w4[8] = {v1.x, v1.y, v1.z, v1.w, v2.x, v2.y, v2.z, v2.w};
        #pragma unroll
        for (int h = 0; h < 8; h++) {
            float2 a = up2f8((uint16_t)(w4[h] & 0xFFFF));
            float2 b2 = up2f8((uint16_t)(w4[h] >> 16));
            s += (a.x + a.y) + (b2.x + b2.y);
        }
    }
    __shared__ float sh[4];
    #pragma unroll
    for (int o = 16; o > 0; o >>= 1) s += __shfl_xor_sync(0xffffffffu, s, o);
    const int w = threadIdx.x >> 5, l = threadIdx.x & 31;
    if (l == 0) sh[w] = s;
    __syncthreads();
    if ((threadIdx.x & 63) == 0) {
        float v = sh[half * 2] + sh[half * 2 + 1];
        g_conf[row] = fdec(g_confbits[row]);
        g_rinv[row] = 1.0f / v;
    }
}

// ---------------------------------------------------------------------------
// Kernel 4: refined = (E @ F) * rinv ; out = cw*refined + (1-cw)*final.
// fp8 e4m3 QMMA m16n8k32. 128x128 CTA tile, 4 warps (64x64 warp tile),
// k-chunk 128 bytes, 3-stage pipeline, fragment double-buffering.
// ---------------------------------------------------------------------------
#define KT_OUT (NN / 128)                  // 16 iterations
#define STG8   16384                       // bytes per stage tile (128x128)
#define OUT_SMEM (6 * STG8)                // 98304

__global__ __launch_bounds__(128, 2) void out_mma(const float* __restrict__ fin,
                                                  float* __restrict__ out) {
    extern __shared__ char dsm[];
    unsigned char* Es = (unsigned char*)dsm;          // [3][STG8]
    unsigned char* Fs = Es + 3 * STG8;                // [3][STG8]
    const int b = blockIdx.z;
    const int row0 = blockIdx.y << 7;   // n rows
    const int col0 = blockIdx.x << 7;   // d cols
    const unsigned char* Eb = g_expb + (size_t)b * NN * NN;
    const unsigned char* Tb = g_ftp8 + (size_t)b * DD * NN;

    const int tid = threadIdx.x, lane = tid & 31, wid = tid >> 5;
    const int wm = (wid >> 1) << 6;
    const int wn = (wid & 1) << 6;

    float acc[4][8][4];
    #pragma unroll
    for (int i = 0; i < 4; i++)
        #pragma unroll
        for (int j = 0; j < 8; j++)
            #pragma unroll
            for (int k = 0; k < 4; k++) acc[i][j][k] = 0.f;

    // loader: 1024 16B-chunks per tile, 8 per thread per operand
    #define OUT_LOAD(kt, p_)                                                    \
        do {                                                                    \
            _Pragma("unroll")                                                   \
            for (int q = 0; q < 8; q++) {                                       \
                int ch = tid + 128 * q;                                         \
                int r = ch >> 3, c = ch & 7;                                    \
                int so = off8w(r, c);                                           \
                cpa16(&Es[(p_) * STG8 + so],                                    \
                      Eb + (size_t)(row0 + r) * NN + (kt) + c * 16);            \
                cpa16(&Fs[(p_) * STG8 + so],                                    \
                      Tb + (size_t)(col0 + r) * NN + (kt) + c * 16);            \
            }                                                                   \
        } while (0)

    uint32_t af[2][4][4], bf[2][8][2];

    #define OUT_FRAGS(ks, fb)                                                   \
        do {                                                                    \
            _Pragma("unroll")                                                   \
            for (int i = 0; i < 4; i++) {                                       \
                int row = wm + i * 16 + (lane & 15);                            \
                int c16 = (ks) * 2 + (lane >> 4);                               \
                uint32_t ad = s2u(&Es[p * STG8 + off8w(row, c16)]);             \
                asm volatile("ldmatrix.sync.aligned.m8n8.x4.shared.b16 {%0,%1,%2,%3}, [%4];" \
                    : "=r"(af[fb][i][0]), "=r"(af[fb][i][1]),                   \
                      "=r"(af[fb][i][2]), "=r"(af[fb][i][3]) : "r"(ad));        \
            }                                                                   \
            _Pragma("unroll")                                                   \
            for (int j2 = 0; j2 < 4; j2++) {                                    \
                int row = wn + j2 * 16 + (lane & 7) + (((lane >> 4) & 1) << 3); \
                int c16 = (ks) * 2 + ((lane >> 3) & 1);                         \
                uint32_t bd = s2u(&Fs[p * STG8 + off8w(row, c16)]);             \
                asm volatile("ldmatrix.sync.aligned.m8n8.x4.shared.b16 {%0,%1,%2,%3}, [%4];" \
                    : "=r"(bf[fb][j2 * 2][0]), "=r"(bf[fb][j2 * 2][1]),         \
                      "=r"(bf[fb][j2 * 2 + 1][0]), "=r"(bf[fb][j2 * 2 + 1][1])  \
                    : "r"(bd));                                                 \
            }                                                                   \
        } while (0)

    OUT_LOAD(0, 0);
    CP_COMMIT();
    OUT_LOAD(128, 1);
    CP_COMMIT();

    int p = 0, pw = 2;
    for (int kti = 0; kti < KT_OUT; kti++) {
        CP_WAIT(1);
        __syncthreads();
        if (kti + 2 < KT_OUT) OUT_LOAD((kti + 2) * 128, pw);
        CP_COMMIT();

        OUT_FRAGS(0, 0);
        #pragma unroll
        for (int ks = 0; ks < 4; ks++) {
            if (ks + 1 < 4) OUT_FRAGS(ks + 1, (ks + 1) & 1);
            const int fb = ks & 1;
            #pragma unroll
            for (int i = 0; i < 4; i++)
                #pragma unroll
                for (int j = 0; j < 8; j++)
                    asm volatile(
                        "mma.sync.aligned.m16n8k32.row.col.f32.e4m3.e4m3.f32 "
                        "{%0,%1,%2,%3}, {%4,%5,%6,%7}, {%8,%9}, {%0,%1,%2,%3};"
                        : "+f"(acc[i][j][0]), "+f"(acc[i][j][1]),
                          "+f"(acc[i][j][2]), "+f"(acc[i][j][3])
                        : "r"(af[fb][i][0]), "r"(af[fb][i][1]),
                          "r"(af[fb][i][2]), "r"(af[fb][i][3]),
                          "r"(bf[fb][j][0]), "r"(bf[fb][j][1]));
        }
        p = (p == 2) ? 0 : p + 1;
        pw = (pw == 2) ? 0 : pw + 1;
    }

    const float* F32 = fin + (size_t)b * NN * DD;
    float* O = out + (size_t)b * NN * DD;
    const int gr = lane >> 2, gc = (lane & 3) << 1;
    #pragma unroll
    for (int i = 0; i < 4; i++) {
        #pragma unroll
        for (int half = 0; half < 2; half++) {
            int r = row0 + wm + i * 16 + gr + half * 8;
            const float cw  = g_conf[b * NN + r];
            const float inv = g_rinv[b * NN + r];
            #pragma unroll
            for (int j = 0; j < 8; j++) {
                int c = col0 + wn + j * 8 + gc;
                float2 f = *(const float2*)(F32 + (size_t)r * DD + c);
                float2 o;
                o.x = cw * (acc[i][j][half * 2 + 0] * inv) + (1.0f - cw) * f.x;
                o.y = cw * (acc[i][j][half * 2 + 1] * inv) + (1.0f - cw) * f.y;
                *(float2*)(O + (size_t)r * DD + c) = o;
            }
        }
    }
}

// ---------------------------------------------------------------------------
extern "C" void kernel_launch(void* const* d_in, const int* in_sizes, int n_in,
                              void* d_out, int out_size) {
    const float* final_f = (const float*)d_in[0];
    const float* mid_f   = (const float*)d_in[1];
    float* out = (float*)d_out;

    static int configured = 0;
    if (!configured) {
        cudaFuncSetAttribute(sim_mma, cudaFuncAttributeMaxDynamicSharedMemorySize,
                             SIM_SMEM);
        cudaFuncSetAttribute(out_mma, cudaFuncAttributeMaxDynamicSharedMemorySize,
                             OUT_SMEM);
        configured = 1;
    }

    norm_kernel<<<BATCH * NN, 256>>>(mid_f);
    transpose_fp8<<<dim3(DD / 32, NN / 32, BATCH), dim3(32, 8)>>>(final_f);

    sim_mma<<<dim3(NPAIRS, 1, BATCH), 128, SIM_SMEM>>>();

    rowsum_kernel<<<BATCH * NN / 2, 128>>>();

    out_mma<<<dim3(DD / 128, NN / 128, BATCH), 128, OUT_SMEM>>>(final_f, out);
}

// round 14
// speedup vs baseline: 1.0803x; 1.0351x over previous
#include <cuda_runtime.h>
#include <cuda_bf16.h>
#include <cuda_fp16.h>
#include <cuda_fp8.h>
#include <stdint.h>
#include <stddef.h>
#include <math.h>

#define BATCH 8
#define NN 2048
#define DD 768
#define NTILE 16
#define NPAIRS (NTILE * (NTILE + 1) / 2)   // 136 upper-triangle tiles

// ---------------- device scratch (allocation-free rule) ----------------
__device__ __nv_bfloat16 g_midn[(size_t)BATCH * NN * DD];   // normalized mid (bf16)
__device__ unsigned char g_ftp8[(size_t)BATCH * DD * NN];   // final^T (e4m3), [d][n]
__device__ unsigned char g_expb[(size_t)BATCH * NN * NN];   // e4m3 exp(sim)
__device__ unsigned      g_confbits[BATCH * NN];            // ordered-uint row max
__device__ float         g_conf[BATCH * NN];                // row max (confidence)
__device__ float         g_rinv[BATCH * NN];                // 1 / row sum of exp

__device__ __forceinline__ uint32_t s2u(const void* p) {
    return (uint32_t)__cvta_generic_to_shared(p);
}
__device__ __forceinline__ void cpa16(void* dst, const void* src) {
    asm volatile("cp.async.cg.shared.global [%0], [%1], 16;"
                 :: "r"(s2u(dst)), "l"(src));
}
#define CP_COMMIT() asm volatile("cp.async.commit_group;")
#define CP_WAIT(n)  asm volatile("cp.async.wait_group %0;" :: "n"(n))

// monotonic float<->uint for atomicMax
__device__ __forceinline__ unsigned fenc(float x) {
    unsigned b = __float_as_uint(x);
    return (b & 0x80000000u) ? ~b : (b | 0x80000000u);
}
__device__ __forceinline__ float fdec(unsigned e) {
    unsigned b = (e & 0x80000000u) ? (e ^ 0x80000000u) : ~e;
    return __uint_as_float(b);
}
__device__ __forceinline__ uint32_t pk2f8(float a, float b2) {
    return (uint32_t)__nv_cvt_float2_to_fp8x2(make_float2(a, b2),
                                              __NV_SATFINITE, __NV_E4M3);
}
__device__ __forceinline__ uint32_t pk4f8(float a, float b2, float c, float d) {
    return pk2f8(a, b2) | (pk2f8(c, d) << 16);
}
__device__ __forceinline__ float2 up2f8(uint16_t x) {
    __half2_raw hr = __nv_cvt_fp8x2_to_halfraw2((__nv_fp8x2_storage_t)x, __NV_E4M3);
    return __half22float2(*(__half2*)&hr);
}

// swizzled index (halves) for bf16 tiles: 128 rows x 32 halves (64B rows)
__device__ __forceinline__ int swA(int row, int kh) {
    return (row << 5) | ((((kh >> 3) ^ ((row >> 1) & 3)) << 3));
}
// swizzled byte offset for fp8 tiles with 128B rows (8 x 16B chunks)
__device__ __forceinline__ int off8w(int r, int c16) {
    return (r << 7) | ((((c16) ^ (r & 7)) & 7) << 4);
}

// ---------------------------------------------------------------------------
// Kernel 1 (merged prep): blocks [0, B*NN) L2-normalize mid -> bf16 + reset
// confbits; blocks [B*NN, ...) transpose final fp32 [n][d] -> e4m3 [d][n].
// ---------------------------------------------------------------------------
#define NORM_BLKS (BATCH * NN)
#define TR_BX (DD / 32)                    // 24
#define TR_BY (NN / 32)                    // 64
#define TR_BLKS (TR_BX * TR_BY * BATCH)    // 12288

__global__ void prep_kernel(const float* __restrict__ mid,
                            const float* __restrict__ fin) {
    __shared__ float shmem[32 * 33];
    if (blockIdx.x < NORM_BLKS) {
        const int row = blockIdx.x;
        if (threadIdx.x == 0) g_confbits[row] = fenc(-INFINITY);
        const float* x = mid + (size_t)row * DD;
        __nv_bfloat16* y = g_midn + (size_t)row * DD;

        float s = 0.f;
        for (int i = threadIdx.x; i < DD; i += blockDim.x) {
            float v = x[i];
            s += v * v;
        }
        float* sh = shmem;
        #pragma unroll
        for (int o = 16; o > 0; o >>= 1) s += __shfl_xor_sync(0xffffffffu, s, o);
        const int w = threadIdx.x >> 5, l = threadIdx.x & 31;
        if (l == 0) sh[w] = s;
        __syncthreads();
        if (w == 0) {
            float v = (threadIdx.x < (blockDim.x >> 5)) ? sh[threadIdx.x] : 0.f;
            #pragma unroll
            for (int o = 16; o > 0; o >>= 1) v += __shfl_xor_sync(0xffffffffu, v, o);
            if (threadIdx.x == 0) sh[0] = v;
        }
        __syncthreads();
        const float inv = 1.0f / fmaxf(sqrtf(sh[0]), 1e-12f);
        for (int i = threadIdx.x; i < DD; i += blockDim.x)
            y[i] = __float2bfloat16(x[i] * inv);
    } else {
        const int bid = blockIdx.x - NORM_BLKS;
        const int b = bid / (TR_BX * TR_BY);
        const int rem = bid - b * (TR_BX * TR_BY);
        const int d0 = (rem % TR_BX) * 32, n0 = (rem / TR_BX) * 32;
        const float* F = fin + (size_t)b * NN * DD;
        unsigned char* T = g_ftp8 + (size_t)b * DD * NN;
        float (*t)[33] = (float(*)[33])shmem;
        const int x = threadIdx.x & 31, y = threadIdx.x >> 5;  // 32 x 8
        #pragma unroll
        for (int i = 0; i < 4; i++)
            t[y + 8 * i][x] = F[(size_t)(n0 + y + 8 * i) * DD + d0 + x];
        __syncthreads();
        uint32_t word = pk4f8(t[y * 4 + 0][x], t[y * 4 + 1][x],
                              t[y * 4 + 2][x], t[y * 4 + 3][x]);
        *(uint32_t*)(T + (size_t)(d0 + x) * NN + n0 + y * 4) = word;
    }
}

// ---------------------------------------------------------------------------
// Kernel 2: sim GEMM (upper-triangle tiles, bf16 HMMA). 128x128 CTA tile,
// 4 warps (64x64 warp tile), k-chunk 32 halves, 4-stage pipeline,
// fragment double-buffering. Epilogue: exp(sim) e4m3 + row-max atomics.
// ---------------------------------------------------------------------------
#define KT_SIM (DD / 32)                   // 24 iterations
#define STG    4096                        // halves per stage tile (128x32)
#define SIM_SMEM (128 * 129 * 4)           // 66048 B (>= 8 stage-tiles * 8KB)

__global__ __launch_bounds__(128, 2) void sim_mma() {
    extern __shared__ char dsm[];
    __nv_bfloat16* As = (__nv_bfloat16*)dsm;          // [4][STG]
    __nv_bfloat16* Bs = As + 4 * STG;                 // [4][STG]
    float* T = (float*)dsm;                           // [128][129], reused

    int t = blockIdx.x, bi = 0, rem = NTILE;
    while (t >= rem) { t -= rem; rem--; bi++; }
    const int bj = bi + t;
    const int b = blockIdx.z;
    const int row0 = bi << 7, col0 = bj << 7;
    const bool diag = (bi == bj);
    const __nv_bfloat16* Ab = g_midn + (size_t)b * NN * DD;
    const __nv_bfloat16* Bbase = diag ? As : Bs;      // diag: B operand = A tile

    const int tid = threadIdx.x, lane = tid & 31, wid = tid >> 5;
    const int wm = (wid >> 1) << 6;    // 0, 64
    const int wn = (wid & 1) << 6;     // 0, 64

    float acc[4][8][4];
    #pragma unroll
    for (int i = 0; i < 4; i++)
        #pragma unroll
        for (int j = 0; j < 8; j++)
            #pragma unroll
            for (int k = 0; k < 4; k++) acc[i][j][k] = 0.f;

    #define SIM_LOAD(kt, p_)                                                    \
        do {                                                                    \
            _Pragma("unroll")                                                   \
            for (int q = 0; q < 4; q++) {                                       \
                int ch = tid + 128 * q;                                         \
                int r = ch >> 2, c = ch & 3;                                    \
                int so = (r << 5) | (((c ^ ((r >> 1) & 3))) << 3);              \
                cpa16(&As[(p_) * STG + so],                                     \
                      Ab + (size_t)(row0 + r) * DD + (kt) + c * 8);             \
                if (!diag)                                                      \
                    cpa16(&Bs[(p_) * STG + so],                                 \
                          Ab + (size_t)(col0 + r) * DD + (kt) + c * 8);         \
            }                                                                   \
        } while (0)

    uint32_t af[2][4][4], bf[2][8][2];

    #define SIM_FRAGS(ks, fb)                                                   \
        do {                                                                    \
            _Pragma("unroll")                                                   \
            for (int i = 0; i < 4; i++) {                                       \
                int row = wm + i * 16 + (lane & 15);                            \
                int kh  = (ks) * 16 + ((lane >> 4) << 3);                       \
                uint32_t ad = s2u(&As[p * STG + swA(row, kh)]);                 \
                asm volatile("ldmatrix.sync.aligned.m8n8.x4.shared.b16 {%0,%1,%2,%3}, [%4];" \
                    : "=r"(af[fb][i][0]), "=r"(af[fb][i][1]),                   \
                      "=r"(af[fb][i][2]), "=r"(af[fb][i][3]) : "r"(ad));        \
            }                                                                   \
            _Pragma("unroll")                                                   \
            for (int j2 = 0; j2 < 4; j2++) {                                    \
                int row = wn + j2 * 16 + (lane & 7) + (((lane >> 4) & 1) << 3); \
                int kh  = (ks) * 16 + (((lane >> 3) & 1) << 3);                 \
                uint32_t bd = s2u(&Bbase[p * STG + swA(row, kh)]);              \
                asm volatile("ldmatrix.sync.aligned.m8n8.x4.shared.b16 {%0,%1,%2,%3}, [%4];" \
                    : "=r"(bf[fb][j2 * 2][0]), "=r"(bf[fb][j2 * 2][1]),         \
                      "=r"(bf[fb][j2 * 2 + 1][0]), "=r"(bf[fb][j2 * 2 + 1][1])  \
                    : "r"(bd));                                                 \
            }                                                                   \
        } while (0)

    SIM_LOAD(0, 0);
    CP_COMMIT();
    SIM_LOAD(32, 1);
    CP_COMMIT();
    SIM_LOAD(64, 2);
    CP_COMMIT();

    int p = 0, pw = 3;
    for (int kti = 0; kti < KT_SIM; kti++) {
        CP_WAIT(2);
        __syncthreads();
        if (kti + 3 < KT_SIM) SIM_LOAD((kti + 3) * 32, pw);
        CP_COMMIT();

        SIM_FRAGS(0, 0);
        #pragma unroll
        for (int ks = 0; ks < 2; ks++) {
            if (ks + 1 < 2) SIM_FRAGS(ks + 1, (ks + 1) & 1);
            const int fb = ks & 1;
            #pragma unroll
            for (int i = 0; i < 4; i++)
                #pragma unroll
                for (int j = 0; j < 8; j++)
                    asm volatile(
                        "mma.sync.aligned.m16n8k16.row.col.f32.bf16.bf16.f32 "
                        "{%0,%1,%2,%3}, {%4,%5,%6,%7}, {%8,%9}, {%0,%1,%2,%3};"
                        : "+f"(acc[i][j][0]), "+f"(acc[i][j][1]),
                          "+f"(acc[i][j][2]), "+f"(acc[i][j][3])
                        : "r"(af[fb][i][0]), "r"(af[fb][i][1]),
                          "r"(af[fb][i][2]), "r"(af[fb][i][3]),
                          "r"(bf[fb][j][0]), "r"(bf[fb][j][1]));
        }
        p = (p + 1) & 3;
        pw = (pw + 1) & 3;
    }
    __syncthreads();   // all warps done reading stages before T overwrites them

    // ---- stage fp32 tile (diag zeroed) in SMEM ----
    const int gr = lane >> 2, gc = (lane & 3) << 1;
    #pragma unroll
    for (int i = 0; i < 4; i++) {
        const int rl = wm + i * 16 + gr;
        #pragma unroll
        for (int j = 0; j < 8; j++) {
            const int cl = wn + j * 8 + gc;
            const int gofs = (row0 + rl) - (col0 + cl);
            T[rl * 129 + cl]           = (gofs == 0)  ? 0.f : acc[i][j][0];
            T[rl * 129 + cl + 1]       = (gofs == 1)  ? 0.f : acc[i][j][1];
            T[(rl + 8) * 129 + cl]     = (gofs == -8) ? 0.f : acc[i][j][2];
            T[(rl + 8) * 129 + cl + 1] = (gofs == -7) ? 0.f : acc[i][j][3];
        }
    }
    __syncthreads();

    // ---- row pass: write exp(tile) as e4m3 + row-max atomics ----
    {
        const int rr = tid;                 // one row per thread
        float mx = -INFINITY;
        uint32_t* dst = (uint32_t*)(g_expb + (size_t)b * NN * NN
                                    + (size_t)(row0 + rr) * NN + col0);
        #pragma unroll
        for (int c = 0; c < 128; c += 4) {
            float v0 = T[rr * 129 + c + 0];
            float v1 = T[rr * 129 + c + 1];
            float v2 = T[rr * 129 + c + 2];
            float v3 = T[rr * 129 + c + 3];
            mx = fmaxf(mx, fmaxf(fmaxf(v0, v1), fmaxf(v2, v3)));
            dst[c >> 2] = pk4f8(__expf(v0), __expf(v1), __expf(v2), __expf(v3));
        }
        atomicMax(&g_confbits[b * NN + row0 + rr], fenc(mx));
    }

    // ---- col pass (mirror) for off-diagonal tiles ----
    if (!diag) {
        const int cc = tid;                 // one column per thread
        float mx = -INFINITY;
        uint32_t* dst = (uint32_t*)(g_expb + (size_t)b * NN * NN
                                    + (size_t)(col0 + cc) * NN + row0);
        #pragma unroll
        for (int r = 0; r < 128; r += 4) {
            float v0 = T[(r + 0) * 129 + cc];
            float v1 = T[(r + 1) * 129 + cc];
            float v2 = T[(r + 2) * 129 + cc];
            float v3 = T[(r + 3) * 129 + cc];
            mx = fmaxf(mx, fmaxf(fmaxf(v0, v1), fmaxf(v2, v3)));
            dst[r >> 2] = pk4f8(__expf(v0), __expf(v1), __expf(v2), __expf(v3));
        }
        atomicMax(&g_confbits[b * NN + col0 + cc], fenc(mx));
    }
}

// ---------------------------------------------------------------------------
// Kernel 3: row sums of e4m3 exp -> rinv; 2 rows per block (MLP 2/thread).
// ---------------------------------------------------------------------------
__global__ void rowsum_kernel() {
    const int rbase = blockIdx.x * 2;
    const int half = threadIdx.x >> 6;            // 0/1 -> row within pair
    const int t = threadIdx.x & 63;
    const int row = rbase + half;
    const uint4* p = (const uint4*)(g_expb + (size_t)row * NN) + t * 2;
    uint4 v1 = p[0];
    uint4 v2 = p[1];
    float s = 0.f;
    {
        const uint32_t w4[8] = {v1.x, v1.y, v1.z, v1.w, v2.x, v2.y, v2.z, v2.w};
        #pragma unroll
        for (int h = 0; h < 8; h++) {
            float2 a = up2f8((uint16_t)(w4[h] & 0xFFFF));
            float2 b2 = up2f8((uint16_t)(w4[h] >> 16));
            s += (a.x + a.y) + (b2.x + b2.y);
        }
    }
    __shared__ float sh[4];
    #pragma unroll
    for (int o = 16; o > 0; o >>= 1) s += __shfl_xor_sync(0xffffffffu, s, o);
    const int w = threadIdx.x >> 5, l = threadIdx.x & 31;
    if (l == 0) sh[w] = s;
    __syncthreads();
    if ((threadIdx.x & 63) == 0) {
        float v = sh[half * 2] + sh[half * 2 + 1];
        g_conf[row] = fdec(g_confbits[row]);
        g_rinv[row] = 1.0f / v;
    }
}

// ---------------------------------------------------------------------------
// Kernel 4: refined = (E @ F) * rinv ; out = cw*refined + (1-cw)*final.
// fp8 e4m3 QMMA m16n8k32 with FP16 accumulators. 128x128 CTA tile, 4 warps
// (64x64 warp tile), k-chunk 128 bytes, 3-stage pipeline, frag double-buffer.
// ---------------------------------------------------------------------------
#define KT_OUT (NN / 128)                  // 16 iterations
#define STG8   16384                       // bytes per stage tile (128x128)
#define OUT_SMEM (6 * STG8)                // 98304

__global__ __launch_bounds__(128, 2) void out_mma(const float* __restrict__ fin,
                                                  float* __restrict__ out) {
    extern __shared__ char dsm[];
    unsigned char* Es = (unsigned char*)dsm;          // [3][STG8]
    unsigned char* Fs = Es + 3 * STG8;                // [3][STG8]
    const int b = blockIdx.z;
    const int row0 = blockIdx.y << 7;   // n rows
    const int col0 = blockIdx.x << 7;   // d cols
    const unsigned char* Eb = g_expb + (size_t)b * NN * NN;
    const unsigned char* Tb = g_ftp8 + (size_t)b * DD * NN;

    const int tid = threadIdx.x, lane = tid & 31, wid = tid >> 5;
    const int wm = (wid >> 1) << 6;
    const int wn = (wid & 1) << 6;

    // fp16 accumulators: 2 regs per mma tile (4 halves)
    uint32_t acc[4][8][2];
    #pragma unroll
    for (int i = 0; i < 4; i++)
        #pragma unroll
        for (int j = 0; j < 8; j++) {
            acc[i][j][0] = 0u;
            acc[i][j][1] = 0u;
        }

    // loader: 1024 16B-chunks per tile, 8 per thread per operand
    #define OUT_LOAD(kt, p_)                                                    \
        do {                                                                    \
            _Pragma("unroll")                                                   \
            for (int q = 0; q < 8; q++) {                                       \
                int ch = tid + 128 * q;                                         \
                int r = ch >> 3, c = ch & 7;                                    \
                int so = off8w(r, c);                                           \
                cpa16(&Es[(p_) * STG8 + so],                                    \
                      Eb + (size_t)(row0 + r) * NN + (kt) + c * 16);            \
                cpa16(&Fs[(p_) * STG8 + so],                                    \
                      Tb + (size_t)(col0 + r) * NN + (kt) + c * 16);            \
            }                                                                   \
        } while (0)

    uint32_t af[2][4][4], bf[2][8][2];

    #define OUT_FRAGS(ks, fb)                                                   \
        do {                                                                    \
            _Pragma("unroll")                                                   \
            for (int i = 0; i < 4; i++) {                                       \
                int row = wm + i * 16 + (lane & 15);                            \
                int c16 = (ks) * 2 + (lane >> 4);                               \
                uint32_t ad = s2u(&Es[p * STG8 + off8w(row, c16)]);             \
                asm volatile("ldmatrix.sync.aligned.m8n8.x4.shared.b16 {%0,%1,%2,%3}, [%4];" \
                    : "=r"(af[fb][i][0]), "=r"(af[fb][i][1]),                   \
                      "=r"(af[fb][i][2]), "=r"(af[fb][i][3]) : "r"(ad));        \
            }                                                                   \
            _Pragma("unroll")                                                   \
            for (int j2 = 0; j2 < 4; j2++) {                                    \
                int row = wn + j2 * 16 + (lane & 7) + (((lane >> 4) & 1) << 3); \
                int c16 = (ks) * 2 + ((lane >> 3) & 1);                         \
                uint32_t bd = s2u(&Fs[p * STG8 + off8w(row, c16)]);             \
                asm volatile("ldmatrix.sync.aligned.m8n8.x4.shared.b16 {%0,%1,%2,%3}, [%4];" \
                    : "=r"(bf[fb][j2 * 2][0]), "=r"(bf[fb][j2 * 2][1]),         \
                      "=r"(bf[fb][j2 * 2 + 1][0]), "=r"(bf[fb][j2 * 2 + 1][1])  \
                    : "r"(bd));                                                 \
            }                                                                   \
        } while (0)

    OUT_LOAD(0, 0);
    CP_COMMIT();
    OUT_LOAD(128, 1);
    CP_COMMIT();

    int p = 0, pw = 2;
    for (int kti = 0; kti < KT_OUT; kti++) {
        CP_WAIT(1);
        __syncthreads();
        if (kti + 2 < KT_OUT) OUT_LOAD((kti + 2) * 128, pw);
        CP_COMMIT();

        OUT_FRAGS(0, 0);
        #pragma unroll
        for (int ks = 0; ks < 4; ks++) {
            if (ks + 1 < 4) OUT_FRAGS(ks + 1, (ks + 1) & 1);
            const int fb = ks & 1;
            #pragma unroll
            for (int i = 0; i < 4; i++)
                #pragma unroll
                for (int j = 0; j < 8; j++)
                    asm volatile(
                        "mma.sync.aligned.m16n8k32.row.col.f16.e4m3.e4m3.f16 "
                        "{%0,%1}, {%2,%3,%4,%5}, {%6,%7}, {%0,%1};"
                        : "+r"(acc[i][j][0]), "+r"(acc[i][j][1])
                        : "r"(af[fb][i][0]), "r"(af[fb][i][1]),
                          "r"(af[fb][i][2]), "r"(af[fb][i][3]),
                          "r"(bf[fb][j][0]), "r"(bf[fb][j][1]));
        }
        p = (p == 2) ? 0 : p + 1;
        pw = (pw == 2) ? 0 : pw + 1;
    }

    const float* F32 = fin + (size_t)b * NN * DD;
    float* O = out + (size_t)b * NN * DD;
    const int gr = lane >> 2, gc = (lane & 3) << 1;
    #pragma unroll
    for (int i = 0; i < 4; i++) {
        #pragma unroll
        for (int half = 0; half < 2; half++) {
            int r = row0 + wm + i * 16 + gr + half * 8;
            const float cw  = g_conf[b * NN + r];
            const float inv = g_rinv[b * NN + r];
            #pragma unroll
            for (int j = 0; j < 8; j++) {
                int c = col0 + wn + j * 8 + gc;
                float2 f = *(const float2*)(F32 + (size_t)r * DD + c);
                float2 acc2 = __half22float2(*(__half2*)&acc[i][j][half]);
                float2 o;
                o.x = cw * (acc2.x * inv) + (1.0f - cw) * f.x;
                o.y = cw * (acc2.y * inv) + (1.0f - cw) * f.y;
                *(float2*)(O + (size_t)r * DD + c) = o;
            }
        }
    }
}

// ---------------------------------------------------------------------------
extern "C" void kernel_launch(void* const* d_in, const int* in_sizes, int n_in,
                              void* d_out, int out_size) {
    const float* final_f = (const float*)d_in[0];
    const float* mid_f   = (const float*)d_in[1];
    float* out = (float*)d_out;

    static int configured = 0;
    if (!configured) {
        cudaFuncSetAttribute(sim_mma, cudaFuncAttributeMaxDynamicSharedMemorySize,
                             SIM_SMEM);
        cudaFuncSetAttribute(out_mma, cudaFuncAttributeMaxDynamicSharedMemorySize,
                             OUT_SMEM);
        configured = 1;
    }

    prep_kernel<<<NORM_BLKS + TR_BLKS, 256>>>(mid_f, final_f);

    sim_mma<<<dim3(NPAIRS, 1, BATCH), 128, SIM_SMEM>>>();

    rowsum_kernel<<<BATCH * NN / 2, 128>>>();

    out_mma<<<dim3(DD / 128, NN / 128, BATCH), 128, OUT_SMEM>>>(final_f, out);
}

// round 15
// speedup vs baseline: 1.0841x; 1.0035x over previous
#include <cuda_runtime.h>
#include <cuda_bf16.h>
#include <cuda_fp16.h>
#include <cuda_fp8.h>
#include <stdint.h>
#include <stddef.h>
#include <math.h>

#define BATCH 8
#define NN 2048
#define DD 768
#define NTILE 16
#define NPAIRS (NTILE * (NTILE + 1) / 2)   // 136 upper-triangle tiles

// ---------------- device scratch (allocation-free rule) ----------------
__device__ __nv_bfloat16 g_midn[(size_t)BATCH * NN * DD];   // normalized mid (bf16)
__device__ unsigned char g_ftp8[(size_t)BATCH * DD * NN];   // final^T (e4m3), [d][n]
__device__ unsigned char g_expb[(size_t)BATCH * NN * NN];   // e4m3 exp(sim)
__device__ unsigned      g_confbits[BATCH * NN];            // ordered-uint row max
__device__ float         g_conf[BATCH * NN];                // row max (confidence)
__device__ float         g_rinv[BATCH * NN];                // 1 / row sum of exp

__device__ __forceinline__ uint32_t s2u(const void* p) {
    return (uint32_t)__cvta_generic_to_shared(p);
}
__device__ __forceinline__ void cpa16(void* dst, const void* src) {
    asm volatile("cp.async.cg.shared.global [%0], [%1], 16;"
                 :: "r"(s2u(dst)), "l"(src));
}
#define CP_COMMIT() asm volatile("cp.async.commit_group;")
#define CP_WAIT(n)  asm volatile("cp.async.wait_group %0;" :: "n"(n))

// monotonic float<->uint for atomicMax
__device__ __forceinline__ unsigned fenc(float x) {
    unsigned b = __float_as_uint(x);
    return (b & 0x80000000u) ? ~b : (b | 0x80000000u);
}
__device__ __forceinline__ float fdec(unsigned e) {
    unsigned b = (e & 0x80000000u) ? (e ^ 0x80000000u) : ~e;
    return __uint_as_float(b);
}
__device__ __forceinline__ uint32_t pk2f8(float a, float b2) {
    return (uint32_t)__nv_cvt_float2_to_fp8x2(make_float2(a, b2),
                                              __NV_SATFINITE, __NV_E4M3);
}
__device__ __forceinline__ uint32_t pk4f8(float a, float b2, float c, float d) {
    return pk2f8(a, b2) | (pk2f8(c, d) << 16);
}
__device__ __forceinline__ float2 up2f8(uint16_t x) {
    __half2_raw hr = __nv_cvt_fp8x2_to_halfraw2((__nv_fp8x2_storage_t)x, __NV_E4M3);
    return __half22float2(*(__half2*)&hr);
}

// swizzled index (halves) for bf16 tiles: 128 rows x 32 halves (64B rows)
__device__ __forceinline__ int swA(int row, int kh) {
    return (row << 5) | ((((kh >> 3) ^ ((row >> 1) & 3)) << 3));
}
// swizzled byte offset for fp8 tiles: 128 rows x 64 bytes, 16B chunks
__device__ __forceinline__ int off8(int r, int c16) {
    return (r << 6) | ((((c16) ^ ((r >> 1) & 3)) & 3) << 4);
}

// ---------------------------------------------------------------------------
// Kernel 1 (merged prep): blocks [0, B*NN) L2-normalize mid -> bf16 + reset
// confbits; blocks [B*NN, ...) transpose final fp32 [n][d] -> e4m3 [d][n].
// ---------------------------------------------------------------------------
#define NORM_BLKS (BATCH * NN)
#define TR_BX (DD / 32)                    // 24
#define TR_BY (NN / 32)                    // 64
#define TR_BLKS (TR_BX * TR_BY * BATCH)    // 12288

__global__ void prep_kernel(const float* __restrict__ mid,
                            const float* __restrict__ fin) {
    __shared__ float shmem[32 * 33];
    if (blockIdx.x < NORM_BLKS) {
        const int row = blockIdx.x;
        if (threadIdx.x == 0) g_confbits[row] = fenc(-INFINITY);
        const float* x = mid + (size_t)row * DD;
        __nv_bfloat16* y = g_midn + (size_t)row * DD;

        float s = 0.f;
        for (int i = threadIdx.x; i < DD; i += blockDim.x) {
            float v = x[i];
            s += v * v;
        }
        float* sh = shmem;
        #pragma unroll
        for (int o = 16; o > 0; o >>= 1) s += __shfl_xor_sync(0xffffffffu, s, o);
        const int w = threadIdx.x >> 5, l = threadIdx.x & 31;
        if (l == 0) sh[w] = s;
        __syncthreads();
        if (w == 0) {
            float v = (threadIdx.x < (blockDim.x >> 5)) ? sh[threadIdx.x] : 0.f;
            #pragma unroll
            for (int o = 16; o > 0; o >>= 1) v += __shfl_xor_sync(0xffffffffu, v, o);
            if (threadIdx.x == 0) sh[0] = v;
        }
        __syncthreads();
        const float inv = 1.0f / fmaxf(sqrtf(sh[0]), 1e-12f);
        for (int i = threadIdx.x; i < DD; i += blockDim.x)
            y[i] = __float2bfloat16(x[i] * inv);
    } else {
        const int bid = blockIdx.x - NORM_BLKS;
        const int b = bid / (TR_BX * TR_BY);
        const int rem = bid - b * (TR_BX * TR_BY);
        const int d0 = (rem % TR_BX) * 32, n0 = (rem / TR_BX) * 32;
        const float* F = fin + (size_t)b * NN * DD;
        unsigned char* T = g_ftp8 + (size_t)b * DD * NN;
        float (*t)[33] = (float(*)[33])shmem;
        const int x = threadIdx.x & 31, y = threadIdx.x >> 5;  // 32 x 8
        #pragma unroll
        for (int i = 0; i < 4; i++)
            t[y + 8 * i][x] = F[(size_t)(n0 + y + 8 * i) * DD + d0 + x];
        __syncthreads();
        uint32_t word = pk4f8(t[y * 4 + 0][x], t[y * 4 + 1][x],
                              t[y * 4 + 2][x], t[y * 4 + 3][x]);
        *(uint32_t*)(T + (size_t)(d0 + x) * NN + n0 + y * 4) = word;
    }
}

// ---------------------------------------------------------------------------
// Kernel 2: sim GEMM (upper-triangle tiles, bf16 HMMA). 128x128 CTA tile,
// 4 warps (64x64 warp tile), k-chunk 32 halves, 4-stage pipeline,
// fragment double-buffering. Epilogue: exp(sim) e4m3 + row-max atomics.
// ---------------------------------------------------------------------------
#define KT_SIM (DD / 32)                   // 24 iterations
#define STG    4096                        // halves per stage tile (128x32)
#define SIM_SMEM (128 * 129 * 4)           // 66048 B (>= 8 stage-tiles * 8KB)

__global__ __launch_bounds__(128, 2) void sim_mma() {
    extern __shared__ char dsm[];
    __nv_bfloat16* As = (__nv_bfloat16*)dsm;          // [4][STG]
    __nv_bfloat16* Bs = As + 4 * STG;                 // [4][STG]
    float* T = (float*)dsm;                           // [128][129], reused

    int t = blockIdx.x, bi = 0, rem = NTILE;
    while (t >= rem) { t -= rem; rem--; bi++; }
    const int bj = bi + t;
    const int b = blockIdx.z;
    const int row0 = bi << 7, col0 = bj << 7;
    const bool diag = (bi == bj);
    const __nv_bfloat16* Ab = g_midn + (size_t)b * NN * DD;
    const __nv_bfloat16* Bbase = diag ? As : Bs;      // diag: B operand = A tile

    const int tid = threadIdx.x, lane = tid & 31, wid = tid >> 5;
    const int wm = (wid >> 1) << 6;    // 0, 64
    const int wn = (wid & 1) << 6;     // 0, 64

    float acc[4][8][4];
    #pragma unroll
    for (int i = 0; i < 4; i++)
        #pragma unroll
        for (int j = 0; j < 8; j++)
            #pragma unroll
            for (int k = 0; k < 4; k++) acc[i][j][k] = 0.f;

    #define SIM_LOAD(kt, p_)                                                    \
        do {                                                                    \
            _Pragma("unroll")                                                   \
            for (int q = 0; q < 4; q++) {                                       \
                int ch = tid + 128 * q;                                         \
                int r = ch >> 2, c = ch & 3;                                    \
                int so = (r << 5) | (((c ^ ((r >> 1) & 3))) << 3);              \
                cpa16(&As[(p_) * STG + so],                                     \
                      Ab + (size_t)(row0 + r) * DD + (kt) + c * 8);             \
                if (!diag)                                                      \
                    cpa16(&Bs[(p_) * STG + so],                                 \
                          Ab + (size_t)(col0 + r) * DD + (kt) + c * 8);         \
            }                                                                   \
        } while (0)

    uint32_t af[2][4][4], bf[2][8][2];

    #define SIM_FRAGS(ks, fb)                                                   \
        do {                                                                    \
            _Pragma("unroll")                                                   \
            for (int i = 0; i < 4; i++) {                                       \
                int row = wm + i * 16 + (lane & 15);                            \
                int kh  = (ks) * 16 + ((lane >> 4) << 3);                       \
                uint32_t ad = s2u(&As[p * STG + swA(row, kh)]);                 \
                asm volatile("ldmatrix.sync.aligned.m8n8.x4.shared.b16 {%0,%1,%2,%3}, [%4];" \
                    : "=r"(af[fb][i][0]), "=r"(af[fb][i][1]),                   \
                      "=r"(af[fb][i][2]), "=r"(af[fb][i][3]) : "r"(ad));        \
            }                                                                   \
            _Pragma("unroll")                                                   \
            for (int j2 = 0; j2 < 4; j2++) {                                    \
                int row = wn + j2 * 16 + (lane & 7) + (((lane >> 4) & 1) << 3); \
                int kh  = (ks) * 16 + (((lane >> 3) & 1) << 3);                 \
                uint32_t bd = s2u(&Bbase[p * STG + swA(row, kh)]);              \
                asm volatile("ldmatrix.sync.aligned.m8n8.x4.shared.b16 {%0,%1,%2,%3}, [%4];" \
                    : "=r"(bf[fb][j2 * 2][0]), "=r"(bf[fb][j2 * 2][1]),         \
                      "=r"(bf[fb][j2 * 2 + 1][0]), "=r"(bf[fb][j2 * 2 + 1][1])  \
                    : "r"(bd));                                                 \
            }                                                                   \
        } while (0)

    SIM_LOAD(0, 0);
    CP_COMMIT();
    SIM_LOAD(32, 1);
    CP_COMMIT();
    SIM_LOAD(64, 2);
    CP_COMMIT();

    int p = 0, pw = 3;
    for (int kti = 0; kti < KT_SIM; kti++) {
        CP_WAIT(2);
        __syncthreads();
        if (kti + 3 < KT_SIM) SIM_LOAD((kti + 3) * 32, pw);
        CP_COMMIT();

        SIM_FRAGS(0, 0);
        #pragma unroll
        for (int ks = 0; ks < 2; ks++) {
            if (ks + 1 < 2) SIM_FRAGS(ks + 1, (ks + 1) & 1);
            const int fb = ks & 1;
            #pragma unroll
            for (int i = 0; i < 4; i++)
                #pragma unroll
                for (int j = 0; j < 8; j++)
                    asm volatile(
                        "mma.sync.aligned.m16n8k16.row.col.f32.bf16.bf16.f32 "
                        "{%0,%1,%2,%3}, {%4,%5,%6,%7}, {%8,%9}, {%0,%1,%2,%3};"
                        : "+f"(acc[i][j][0]), "+f"(acc[i][j][1]),
                          "+f"(acc[i][j][2]), "+f"(acc[i][j][3])
                        : "r"(af[fb][i][0]), "r"(af[fb][i][1]),
                          "r"(af[fb][i][2]), "r"(af[fb][i][3]),
                          "r"(bf[fb][j][0]), "r"(bf[fb][j][1]));
        }
        p = (p + 1) & 3;
        pw = (pw + 1) & 3;
    }
    __syncthreads();   // all warps done reading stages before T overwrites them

    // ---- stage fp32 tile (diag zeroed) in SMEM ----
    const int gr = lane >> 2, gc = (lane & 3) << 1;
    #pragma unroll
    for (int i = 0; i < 4; i++) {
        const int rl = wm + i * 16 + gr;
        #pragma unroll
        for (int j = 0; j < 8; j++) {
            const int cl = wn + j * 8 + gc;
            const int gofs = (row0 + rl) - (col0 + cl);
            T[rl * 129 + cl]           = (gofs == 0)  ? 0.f : acc[i][j][0];
            T[rl * 129 + cl + 1]       = (gofs == 1)  ? 0.f : acc[i][j][1];
            T[(rl + 8) * 129 + cl]     = (gofs == -8) ? 0.f : acc[i][j][2];
            T[(rl + 8) * 129 + cl + 1] = (gofs == -7) ? 0.f : acc[i][j][3];
        }
    }
    __syncthreads();

    // ---- row pass: write exp(tile) as e4m3 + row-max atomics ----
    {
        const int rr = tid;                 // one row per thread
        float mx = -INFINITY;
        uint32_t* dst = (uint32_t*)(g_expb + (size_t)b * NN * NN
                                    + (size_t)(row0 + rr) * NN + col0);
        #pragma unroll
        for (int c = 0; c < 128; c += 4) {
            float v0 = T[rr * 129 + c + 0];
            float v1 = T[rr * 129 + c + 1];
            float v2 = T[rr * 129 + c + 2];
            float v3 = T[rr * 129 + c + 3];
            mx = fmaxf(mx, fmaxf(fmaxf(v0, v1), fmaxf(v2, v3)));
            dst[c >> 2] = pk4f8(__expf(v0), __expf(v1), __expf(v2), __expf(v3));
        }
        atomicMax(&g_confbits[b * NN + row0 + rr], fenc(mx));
    }

    // ---- col pass (mirror) for off-diagonal tiles ----
    if (!diag) {
        const int cc = tid;                 // one column per thread
        float mx = -INFINITY;
        uint32_t* dst = (uint32_t*)(g_expb + (size_t)b * NN * NN
                                    + (size_t)(col0 + cc) * NN + row0);
        #pragma unroll
        for (int r = 0; r < 128; r += 4) {
            float v0 = T[(r + 0) * 129 + cc];
            float v1 = T[(r + 1) * 129 + cc];
            float v2 = T[(r + 2) * 129 + cc];
            float v3 = T[(r + 3) * 129 + cc];
            mx = fmaxf(mx, fmaxf(fmaxf(v0, v1), fmaxf(v2, v3)));
            dst[r >> 2] = pk4f8(__expf(v0), __expf(v1), __expf(v2), __expf(v3));
        }
        atomicMax(&g_confbits[b * NN + col0 + cc], fenc(mx));
    }
}

// ---------------------------------------------------------------------------
// Kernel 3: row sums of e4m3 exp -> rinv; 2 rows per block (MLP 2/thread).
// ---------------------------------------------------------------------------
__global__ void rowsum_kernel() {
    const int rbase = blockIdx.x * 2;
    const int half = threadIdx.x >> 6;            // 0/1 -> row within pair
    const int t = threadIdx.x & 63;
    const int row = rbase + half;
    const uint4* p = (const uint4*)(g_expb + (size_t)row * NN) + t * 2;
    uint4 v1 = p[0];
    uint4 v2 = p[1];
    float s = 0.f;
    {
        const uint32_t w4[8] = {v1.x, v1.y, v1.z, v1.w, v2.x, v2.y, v2.z, v2.w};
        #pragma unroll
        for (int h = 0; h < 8; h++) {
            float2 a = up2f8((uint16_t)(w4[h] & 0xFFFF));
            float2 b2 = up2f8((uint16_t)(w4[h] >> 16));
            s += (a.x + a.y) + (b2.x + b2.y);
        }
    }
    __shared__ float sh[4];
    #pragma unroll
    for (int o = 16; o > 0; o >>= 1) s += __shfl_xor_sync(0xffffffffu, s, o);
    const int w = threadIdx.x >> 5, l = threadIdx.x & 31;
    if (l == 0) sh[w] = s;
    __syncthreads();
    if ((threadIdx.x & 63) == 0) {
        float v = sh[half * 2] + sh[half * 2 + 1];
        g_conf[row] = fdec(g_confbits[row]);
        g_rinv[row] = 1.0f / v;
    }
}

// ---------------------------------------------------------------------------
// Kernel 4: refined = (E @ F) * rinv ; out = cw*refined + (1-cw)*final.
// fp8 e4m3 QMMA m16n8k32, FP16 accumulators, single frag buffer,
// k-chunk 64 bytes, 3-stage pipeline, 48KB SMEM, 3 CTAs/SM target.
// ---------------------------------------------------------------------------
#define KT_OUT (NN / 64)                   // 32 iterations
#define STG8   8192                        // bytes per stage tile (128x64)
#define OUT_SMEM (6 * STG8)                // 49152

__global__ __launch_bounds__(128, 3) void out_mma(const float* __restrict__ fin,
                                                  float* __restrict__ out) {
    extern __shared__ char dsm[];
    unsigned char* Es = (unsigned char*)dsm;          // [3][STG8]
    unsigned char* Fs = Es + 3 * STG8;                // [3][STG8]
    const int b = blockIdx.z;
    const int row0 = blockIdx.y << 7;   // n rows
    const int col0 = blockIdx.x << 7;   // d cols
    const unsigned char* Eb = g_expb + (size_t)b * NN * NN;
    const unsigned char* Tb = g_ftp8 + (size_t)b * DD * NN;

    const int tid = threadIdx.x, lane = tid & 31, wid = tid >> 5;
    const int wm = (wid >> 1) << 6;
    const int wn = (wid & 1) << 6;

    // fp16 accumulators: 2 regs per mma tile (4 halves)
    uint32_t acc[4][8][2];
    #pragma unroll
    for (int i = 0; i < 4; i++)
        #pragma unroll
        for (int j = 0; j < 8; j++) {
            acc[i][j][0] = 0u;
            acc[i][j][1] = 0u;
        }

    // loader: 512 16B chunks per tile, 4 per thread per operand
    #define OUT_LOAD(kt, p_)                                                    \
        do {                                                                    \
            _Pragma("unroll")                                                   \
            for (int q = 0; q < 4; q++) {                                       \
                int ch = tid + 128 * q;                                         \
                int r = ch >> 2, c = ch & 3;                                    \
                int so = off8(r, c);                                            \
                cpa16(&Es[(p_) * STG8 + so],                                    \
                      Eb + (size_t)(row0 + r) * NN + (kt) + c * 16);            \
                cpa16(&Fs[(p_) * STG8 + so],                                    \
                      Tb + (size_t)(col0 + r) * NN + (kt) + c * 16);            \
            }                                                                   \
        } while (0)

    OUT_LOAD(0, 0);
    CP_COMMIT();
    OUT_LOAD(64, 1);
    CP_COMMIT();

    int p = 0, pw = 2;
    for (int kti = 0; kti < KT_OUT; kti++) {
        CP_WAIT(1);
        __syncthreads();
        if (kti + 2 < KT_OUT) OUT_LOAD((kti + 2) * 64, pw);
        CP_COMMIT();

        #pragma unroll
        for (int ks = 0; ks < 2; ks++) {
            uint32_t af[4][4];
            #pragma unroll
            for (int i = 0; i < 4; i++) {
                int row = wm + i * 16 + (lane & 15);
                int c16 = ks * 2 + (lane >> 4);
                uint32_t ad = s2u(&Es[p * STG8 + off8(row, c16)]);
                asm volatile("ldmatrix.sync.aligned.m8n8.x4.shared.b16 {%0,%1,%2,%3}, [%4];"
                    : "=r"(af[i][0]), "=r"(af[i][1]), "=r"(af[i][2]), "=r"(af[i][3])
                    : "r"(ad));
            }
            uint32_t bfr[8][2];
            #pragma unroll
            for (int j2 = 0; j2 < 4; j2++) {
                int row = wn + j2 * 16 + (lane & 7) + (((lane >> 4) & 1) << 3);
                int c16 = ks * 2 + ((lane >> 3) & 1);
                uint32_t bd = s2u(&Fs[p * STG8 + off8(row, c16)]);
                asm volatile("ldmatrix.sync.aligned.m8n8.x4.shared.b16 {%0,%1,%2,%3}, [%4];"
                    : "=r"(bfr[j2 * 2][0]), "=r"(bfr[j2 * 2][1]),
                      "=r"(bfr[j2 * 2 + 1][0]), "=r"(bfr[j2 * 2 + 1][1])
                    : "r"(bd));
            }
            #pragma unroll
            for (int i = 0; i < 4; i++)
                #pragma unroll
                for (int j = 0; j < 8; j++)
                    asm volatile(
                        "mma.sync.aligned.m16n8k32.row.col.f16.e4m3.e4m3.f16 "
                        "{%0,%1}, {%2,%3,%4,%5}, {%6,%7}, {%0,%1};"
                        : "+r"(acc[i][j][0]), "+r"(acc[i][j][1])
                        : "r"(af[i][0]), "r"(af[i][1]), "r"(af[i][2]), "r"(af[i][3]),
                          "r"(bfr[j][0]), "r"(bfr[j][1]));
        }
        p = (p == 2) ? 0 : p + 1;
        pw = (pw == 2) ? 0 : pw + 1;
    }

    const float* F32 = fin + (size_t)b * NN * DD;
    float* O = out + (size_t)b * NN * DD;
    const int gr = lane >> 2, gc = (lane & 3) << 1;
    #pragma unroll
    for (int i = 0; i < 4; i++) {
        #pragma unroll
        for (int half = 0; half < 2; half++) {
            int r = row0 + wm + i * 16 + gr + half * 8;
            const float cw  = g_conf[b * NN + r];
            const float inv = g_rinv[b * NN + r];
            #pragma unroll
            for (int j = 0; j < 8; j++) {
                int c = col0 + wn + j * 8 + gc;
                float2 f = *(const float2*)(F32 + (size_t)r * DD + c);
                float2 acc2 = __half22float2(*(__half2*)&acc[i][j][half]);
                float2 o;
                o.x = cw * (acc2.x * inv) + (1.0f - cw) * f.x;
                o.y = cw * (acc2.y * inv) + (1.0f - cw) * f.y;
                *(float2*)(O + (size_t)r * DD + c) = o;
            }
        }
    }
}

// ---------------------------------------------------------------------------
extern "C" void kernel_launch(void* const* d_in, const int* in_sizes, int n_in,
                              void* d_out, int out_size) {
    const float* final_f = (const float*)d_in[0];
    const float* mid_f   = (const float*)d_in[1];
    float* out = (float*)d_out;

    static int configured = 0;
    if (!configured) {
        cudaFuncSetAttribute(sim_mma, cudaFuncAttributeMaxDynamicSharedMemorySize,
                             SIM_SMEM);
        cudaFuncSetAttribute(out_mma, cudaFuncAttributeMaxDynamicSharedMemorySize,
                             OUT_SMEM);
        configured = 1;
    }

    prep_kernel<<<NORM_BLKS + TR_BLKS, 256>>>(mid_f, final_f);

    sim_mma<<<dim3(NPAIRS, 1, BATCH), 128, SIM_SMEM>>>();

    rowsum_kernel<<<BATCH * NN / 2, 128>>>();

    out_mma<<<dim3(DD / 128, NN / 128, BATCH), 128, OUT_SMEM>>>(final_f, out);
}

// round 16
// speedup vs baseline: 1.1388x; 1.0505x over previous
#include <cuda_runtime.h>
#include <cuda_bf16.h>
#include <cuda_fp16.h>
#include <cuda_fp8.h>
#include <stdint.h>
#include <stddef.h>
#include <math.h>

#define BATCH 8
#define NN 2048
#define DD 768
#define NTILE 16
#define NPAIRS (NTILE * (NTILE + 1) / 2)   // 136 upper-triangle tiles

// ---------------- device scratch (allocation-free rule) ----------------
__device__ __nv_bfloat16 g_midn[(size_t)BATCH * NN * DD];   // normalized mid (bf16)
__device__ unsigned char g_ftp8[(size_t)BATCH * DD * NN];   // final^T (e4m3), [d][n]
__device__ unsigned char g_expb[(size_t)BATCH * NN * NN];   // e4m3 exp(sim)
__device__ unsigned      g_confbits[BATCH * NN];            // ordered-uint row max
__device__ float         g_rowsumf[BATCH * NN];             // fp32 row sum of exp

__device__ __forceinline__ uint32_t s2u(const void* p) {
    return (uint32_t)__cvta_generic_to_shared(p);
}
__device__ __forceinline__ void cpa16(void* dst, const void* src) {
    asm volatile("cp.async.cg.shared.global [%0], [%1], 16;"
                 :: "r"(s2u(dst)), "l"(src));
}
#define CP_COMMIT() asm volatile("cp.async.commit_group;")
#define CP_WAIT(n)  asm volatile("cp.async.wait_group %0;" :: "n"(n))

// monotonic float<->uint for atomicMax
__device__ __forceinline__ unsigned fenc(float x) {
    unsigned b = __float_as_uint(x);
    return (b & 0x80000000u) ? ~b : (b | 0x80000000u);
}
__device__ __forceinline__ float fdec(unsigned e) {
    unsigned b = (e & 0x80000000u) ? (e ^ 0x80000000u) : ~e;
    return __uint_as_float(b);
}
__device__ __forceinline__ uint32_t pk2f8(float a, float b2) {
    return (uint32_t)__nv_cvt_float2_to_fp8x2(make_float2(a, b2),
                                              __NV_SATFINITE, __NV_E4M3);
}
__device__ __forceinline__ uint32_t pk4f8(float a, float b2, float c, float d) {
    return pk2f8(a, b2) | (pk2f8(c, d) << 16);
}

// swizzled byte offset for fp8 tiles: 128 rows x 64 bytes, 16B chunks
__device__ __forceinline__ int off8(int r, int c16) {
    return (r << 6) | ((((c16) ^ ((r >> 1) & 3)) & 3) << 4);
}
// swizzled index (halves) for bf16 tiles with 64-half (128B) rows, 8-half chunks
__device__ __forceinline__ int swW(int row, int kc) {
    return (row << 6) | (((kc ^ (row & 7)) & 7) << 3);
}

// ---------------------------------------------------------------------------
// Kernel 1 (merged prep): blocks [0, B*NN) L2-normalize mid -> bf16 + reset
// confbits/rowsum; blocks [B*NN, ...) transpose final fp32 [n][d] -> e4m3.
// ---------------------------------------------------------------------------
#define NORM_BLKS (BATCH * NN)
#define TR_BX (DD / 32)                    // 24
#define TR_BY (NN / 32)                    // 64
#define TR_BLKS (TR_BX * TR_BY * BATCH)    // 12288

__global__ void prep_kernel(const float* __restrict__ mid,
                            const float* __restrict__ fin) {
    __shared__ float shmem[32 * 33];
    if (blockIdx.x < NORM_BLKS) {
        const int row = blockIdx.x;
        if (threadIdx.x == 0) {
            g_confbits[row] = fenc(-INFINITY);
            g_rowsumf[row] = 0.f;
        }
        const float* x = mid + (size_t)row * DD;
        __nv_bfloat16* y = g_midn + (size_t)row * DD;

        float s = 0.f;
        for (int i = threadIdx.x; i < DD; i += blockDim.x) {
            float v = x[i];
            s += v * v;
        }
        float* sh = shmem;
        #pragma unroll
        for (int o = 16; o > 0; o >>= 1) s += __shfl_xor_sync(0xffffffffu, s, o);
        const int w = threadIdx.x >> 5, l = threadIdx.x & 31;
        if (l == 0) sh[w] = s;
        __syncthreads();
        if (w == 0) {
            float v = (threadIdx.x < (blockDim.x >> 5)) ? sh[threadIdx.x] : 0.f;
            #pragma unroll
            for (int o = 16; o > 0; o >>= 1) v += __shfl_xor_sync(0xffffffffu, v, o);
            if (threadIdx.x == 0) sh[0] = v;
        }
        __syncthreads();
        const float inv = 1.0f / fmaxf(sqrtf(sh[0]), 1e-12f);
        for (int i = threadIdx.x; i < DD; i += blockDim.x)
            y[i] = __float2bfloat16(x[i] * inv);
    } else {
        const int bid = blockIdx.x - NORM_BLKS;
        const int b = bid / (TR_BX * TR_BY);
        const int rem = bid - b * (TR_BX * TR_BY);
        const int d0 = (rem % TR_BX) * 32, n0 = (rem / TR_BX) * 32;
        const float* F = fin + (size_t)b * NN * DD;
        unsigned char* T = g_ftp8 + (size_t)b * DD * NN;
        float (*t)[33] = (float(*)[33])shmem;
        const int x = threadIdx.x & 31, y = threadIdx.x >> 5;  // 32 x 8
        #pragma unroll
        for (int i = 0; i < 4; i++)
            t[y + 8 * i][x] = F[(size_t)(n0 + y + 8 * i) * DD + d0 + x];
        __syncthreads();
        uint32_t word = pk4f8(t[y * 4 + 0][x], t[y * 4 + 1][x],
                              t[y * 4 + 2][x], t[y * 4 + 3][x]);
        *(uint32_t*)(T + (size_t)(d0 + x) * NN + n0 + y * 4) = word;
    }
}

// ---------------------------------------------------------------------------
// Kernel 2: sim GEMM (upper-triangle tiles, bf16 HMMA). 128x128 CTA tile,
// 4 warps (64x64 warp tile), k-chunk 64 halves (128B rows), 3-stage pipeline,
// fragment double-buffering. Epilogue: exp(sim) e4m3 + row-max atomics +
// fused partial row sums (atomicAdd).
// ---------------------------------------------------------------------------
#define KT_SIM (DD / 64)                   // 12 iterations
#define STG    8192                        // halves per stage tile (128x64)
#define SIM_SMEM (6 * STG * 2)             // 98304 B (>= T buffer 66048)

__global__ __launch_bounds__(128, 2) void sim_mma() {
    extern __shared__ char dsm[];
    __nv_bfloat16* As = (__nv_bfloat16*)dsm;          // [3][STG]
    __nv_bfloat16* Bs = As + 3 * STG;                 // [3][STG]
    float* T = (float*)dsm;                           // [128][129], reused

    int t = blockIdx.x, bi = 0, rem = NTILE;
    while (t >= rem) { t -= rem; rem--; bi++; }
    const int bj = bi + t;
    const int b = blockIdx.z;
    const int row0 = bi << 7, col0 = bj << 7;
    const bool diag = (bi == bj);
    const __nv_bfloat16* Ab = g_midn + (size_t)b * NN * DD;
    const __nv_bfloat16* Bbase = diag ? As : Bs;      // diag: B operand = A tile

    const int tid = threadIdx.x, lane = tid & 31, wid = tid >> 5;
    const int wm = (wid >> 1) << 6;    // 0, 64
    const int wn = (wid & 1) << 6;     // 0, 64

    float acc[4][8][4];
    #pragma unroll
    for (int i = 0; i < 4; i++)
        #pragma unroll
        for (int j = 0; j < 8; j++)
            #pragma unroll
            for (int k = 0; k < 4; k++) acc[i][j][k] = 0.f;

    // loader: 1024 16B-chunks per tile, 8 per thread per operand
    #define SIM_LOAD(kt, p_)                                                    \
        do {                                                                    \
            _Pragma("unroll")                                                   \
            for (int q = 0; q < 8; q++) {                                       \
                int ch = tid + 128 * q;                                         \
                int r = ch >> 3, c = ch & 7;                                    \
                int so = swW(r, c);                                             \
                cpa16(&As[(p_) * STG + so],                                     \
                      Ab + (size_t)(row0 + r) * DD + (kt) + c * 8);             \
                if (!diag)                                                      \
                    cpa16(&Bs[(p_) * STG + so],                                 \
                          Ab + (size_t)(col0 + r) * DD + (kt) + c * 8);         \
            }                                                                   \
        } while (0)

    uint32_t af[2][4][4], bf[2][8][2];

    #define SIM_FRAGS(ks, fb)                                                   \
        do {                                                                    \
            _Pragma("unroll")                                                   \
            for (int i = 0; i < 4; i++) {                                       \
                int row = wm + i * 16 + (lane & 15);                            \
                int kc  = (ks) * 2 + (lane >> 4);                               \
                uint32_t ad = s2u(&As[p * STG + swW(row, kc)]);                 \
                asm volatile("ldmatrix.sync.aligned.m8n8.x4.shared.b16 {%0,%1,%2,%3}, [%4];" \
                    : "=r"(af[fb][i][0]), "=r"(af[fb][i][1]),                   \
                      "=r"(af[fb][i][2]), "=r"(af[fb][i][3]) : "r"(ad));        \
            }                                                                   \
            _Pragma("unroll")                                                   \
            for (int j2 = 0; j2 < 4; j2++) {                                    \
                int row = wn + j2 * 16 + (lane & 7) + (((lane >> 4) & 1) << 3); \
                int kc  = (ks) * 2 + ((lane >> 3) & 1);                         \
                uint32_t bd = s2u(&Bbase[p * STG + swW(row, kc)]);              \
                asm volatile("ldmatrix.sync.aligned.m8n8.x4.shared.b16 {%0,%1,%2,%3}, [%4];" \
                    : "=r"(bf[fb][j2 * 2][0]), "=r"(bf[fb][j2 * 2][1]),         \
                      "=r"(bf[fb][j2 * 2 + 1][0]), "=r"(bf[fb][j2 * 2 + 1][1])  \
                    : "r"(bd));                                                 \
            }                                                                   \
        } while (0)

    SIM_LOAD(0, 0);
    CP_COMMIT();
    SIM_LOAD(64, 1);
    CP_COMMIT();

    int p = 0, pw = 2;
    for (int kti = 0; kti < KT_SIM; kti++) {
        CP_WAIT(1);
        __syncthreads();
        if (kti + 2 < KT_SIM) SIM_LOAD((kti + 2) * 64, pw);
        CP_COMMIT();

        SIM_FRAGS(0, 0);
        #pragma unroll
        for (int ks = 0; ks < 4; ks++) {
            if (ks + 1 < 4) SIM_FRAGS(ks + 1, (ks + 1) & 1);
            const int fb = ks & 1;
            #pragma unroll
            for (int i = 0; i < 4; i++)
                #pragma unroll
                for (int j = 0; j < 8; j++)
                    asm volatile(
                        "mma.sync.aligned.m16n8k16.row.col.f32.bf16.bf16.f32 "
                        "{%0,%1,%2,%3}, {%4,%5,%6,%7}, {%8,%9}, {%0,%1,%2,%3};"
                        : "+f"(acc[i][j][0]), "+f"(acc[i][j][1]),
                          "+f"(acc[i][j][2]), "+f"(acc[i][j][3])
                        : "r"(af[fb][i][0]), "r"(af[fb][i][1]),
                          "r"(af[fb][i][2]), "r"(af[fb][i][3]),
                          "r"(bf[fb][j][0]), "r"(bf[fb][j][1]));
        }
        p = (p == 2) ? 0 : p + 1;
        pw = (pw == 2) ? 0 : pw + 1;
    }
    __syncthreads();   // all warps done reading stages before T overwrites them

    // ---- stage fp32 tile (diag zeroed) in SMEM ----
    const int gr = lane >> 2, gc = (lane & 3) << 1;
    #pragma unroll
    for (int i = 0; i < 4; i++) {
        const int rl = wm + i * 16 + gr;
        #pragma unroll
        for (int j = 0; j < 8; j++) {
            const int cl = wn + j * 8 + gc;
            const int gofs = (row0 + rl) - (col0 + cl);
            T[rl * 129 + cl]           = (gofs == 0)  ? 0.f : acc[i][j][0];
            T[rl * 129 + cl + 1]       = (gofs == 1)  ? 0.f : acc[i][j][1];
            T[(rl + 8) * 129 + cl]     = (gofs == -8) ? 0.f : acc[i][j][2];
            T[(rl + 8) * 129 + cl + 1] = (gofs == -7) ? 0.f : acc[i][j][3];
        }
    }
    __syncthreads();

    // ---- row pass: exp(tile) -> e4m3, row-max + partial row-sum atomics ----
    {
        const int rr = tid;                 // one row per thread
        float mx = -INFINITY, sm = 0.f;
        uint32_t* dst = (uint32_t*)(g_expb + (size_t)b * NN * NN
                                    + (size_t)(row0 + rr) * NN + col0);
        #pragma unroll
        for (int c = 0; c < 128; c += 4) {
            float v0 = T[rr * 129 + c + 0];
            float v1 = T[rr * 129 + c + 1];
            float v2 = T[rr * 129 + c + 2];
            float v3 = T[rr * 129 + c + 3];
            mx = fmaxf(mx, fmaxf(fmaxf(v0, v1), fmaxf(v2, v3)));
            float e0 = __expf(v0), e1 = __expf(v1);
            float e2 = __expf(v2), e3 = __expf(v3);
            sm += (e0 + e1) + (e2 + e3);
            dst[c >> 2] = pk4f8(e0, e1, e2, e3);
        }
        atomicMax(&g_confbits[b * NN + row0 + rr], fenc(mx));
        atomicAdd(&g_rowsumf[b * NN + row0 + rr], sm);
    }

    // ---- col pass (mirror) for off-diagonal tiles ----
    if (!diag) {
        const int cc = tid;                 // one column per thread
        float mx = -INFINITY, sm = 0.f;
        uint32_t* dst = (uint32_t*)(g_expb + (size_t)b * NN * NN
                                    + (size_t)(col0 + cc) * NN + row0);
        #pragma unroll
        for (int r = 0; r < 128; r += 4) {
            float v0 = T[(r + 0) * 129 + cc];
            float v1 = T[(r + 1) * 129 + cc];
            float v2 = T[(r + 2) * 129 + cc];
            float v3 = T[(r + 3) * 129 + cc];
            mx = fmaxf(mx, fmaxf(fmaxf(v0, v1), fmaxf(v2, v3)));
            float e0 = __expf(v0), e1 = __expf(v1);
            float e2 = __expf(v2), e3 = __expf(v3);
            sm += (e0 + e1) + (e2 + e3);
            dst[r >> 2] = pk4f8(e0, e1, e2, e3);
        }
        atomicMax(&g_confbits[b * NN + col0 + cc], fenc(mx));
        atomicAdd(&g_rowsumf[b * NN + col0 + cc], sm);
    }
}

// ---------------------------------------------------------------------------
// Kernel 3: refined = (E @ F) * rinv ; out = cw*refined + (1-cw)*final.
// fp8 e4m3 QMMA m16n8k32, FP16 accumulators, single frag buffer,
// k-chunk 64 bytes, 3-stage pipeline. conf/rinv read in epilogue.
// ---------------------------------------------------------------------------
#define KT_OUT (NN / 64)                   // 32 iterations
#define STG8   8192                        // bytes per stage tile (128x64)
#define OUT_SMEM (6 * STG8)                // 49152

__global__ __launch_bounds__(128, 3) void out_mma(const float* __restrict__ fin,
                                                  float* __restrict__ out) {
    extern __shared__ char dsm[];
    unsigned char* Es = (unsigned char*)dsm;          // [3][STG8]
    unsigned char* Fs = Es + 3 * STG8;                // [3][STG8]
    const int b = blockIdx.z;
    const int row0 = blockIdx.y << 7;   // n rows
    const int col0 = blockIdx.x << 7;   // d cols
    const unsigned char* Eb = g_expb + (size_t)b * NN * NN;
    const unsigned char* Tb = g_ftp8 + (size_t)b * DD * NN;

    const int tid = threadIdx.x, lane = tid & 31, wid = tid >> 5;
    const int wm = (wid >> 1) << 6;
    const int wn = (wid & 1) << 6;

    // fp16 accumulators: 2 regs per mma tile (4 halves)
    uint32_t acc[4][8][2];
    #pragma unroll
    for (int i = 0; i < 4; i++)
        #pragma unroll
        for (int j = 0; j < 8; j++) {
            acc[i][j][0] = 0u;
            acc[i][j][1] = 0u;
        }

    // loader: 512 16B chunks per tile, 4 per thread per operand
    #define OUT_LOAD(kt, p_)                                                    \
        do {                                                                    \
            _Pragma("unroll")                                                   \
            for (int q = 0; q < 4; q++) {                                       \
                int ch = tid + 128 * q;                                         \
                int r = ch >> 2, c = ch & 3;                                    \
                int so = off8(r, c);                                            \
                cpa16(&Es[(p_) * STG8 + so],                                    \
                      Eb + (size_t)(row0 + r) * NN + (kt) + c * 16);            \
                cpa16(&Fs[(p_) * STG8 + so],                                    \
                      Tb + (size_t)(col0 + r) * NN + (kt) + c * 16);            \
            }                                                                   \
        } while (0)

    OUT_LOAD(0, 0);
    CP_COMMIT();
    OUT_LOAD(64, 1);
    CP_COMMIT();

    int p = 0, pw = 2;
    for (int kti = 0; kti < KT_OUT; kti++) {
        CP_WAIT(1);
        __syncthreads();
        if (kti + 2 < KT_OUT) OUT_LOAD((kti + 2) * 64, pw);
        CP_COMMIT();

        #pragma unroll
        for (int ks = 0; ks < 2; ks++) {
            uint32_t af[4][4];
            #pragma unroll
            for (int i = 0; i < 4; i++) {
                int row = wm + i * 16 + (lane & 15);
                int c16 = ks * 2 + (lane >> 4);
                uint32_t ad = s2u(&Es[p * STG8 + off8(row, c16)]);
                asm volatile("ldmatrix.sync.aligned.m8n8.x4.shared.b16 {%0,%1,%2,%3}, [%4];"
                    : "=r"(af[i][0]), "=r"(af[i][1]), "=r"(af[i][2]), "=r"(af[i][3])
                    : "r"(ad));
            }
            uint32_t bfr[8][2];
            #pragma unroll
            for (int j2 = 0; j2 < 4; j2++) {
                int row = wn + j2 * 16 + (lane & 7) + (((lane >> 4) & 1) << 3);
                int c16 = ks * 2 + ((lane >> 3) & 1);
                uint32_t bd = s2u(&Fs[p * STG8 + off8(row, c16)]);
                asm volatile("ldmatrix.sync.aligned.m8n8.x4.shared.b16 {%0,%1,%2,%3}, [%4];"
                    : "=r"(bfr[j2 * 2][0]), "=r"(bfr[j2 * 2][1]),
                      "=r"(bfr[j2 * 2 + 1][0]), "=r"(bfr[j2 * 2 + 1][1])
                    : "r"(bd));
            }
            #pragma unroll
            for (int i = 0; i < 4; i++)
                #pragma unroll
                for (int j = 0; j < 8; j++)
                    asm volatile(
                        "mma.sync.aligned.m16n8k32.row.col.f16.e4m3.e4m3.f16 "
                        "{%0,%1}, {%2,%3,%4,%5}, {%6,%7}, {%0,%1};"
                        : "+r"(acc[i][j][0]), "+r"(acc[i][j][1])
                        : "r"(af[i][0]), "r"(af[i][1]), "r"(af[i][2]), "r"(af[i][3]),
                          "r"(bfr[j][0]), "r"(bfr[j][1]));
        }
        p = (p == 2) ? 0 : p + 1;
        pw = (pw == 2) ? 0 : pw + 1;
    }

    const float* F32 = fin + (size_t)b * NN * DD;
    float* O = out + (size_t)b * NN * DD;
    const int gr = lane >> 2, gc = (lane & 3) << 1;
    #pragma unroll
    for (int i = 0; i < 4; i++) {
        #pragma unroll
        for (int half = 0; half < 2; half++) {
            int r = row0 + wm + i * 16 + gr + half * 8;
            const float cw  = fdec(g_confbits[b * NN + r]);
            const float inv = 1.0f / g_rowsumf[b * NN + r];
            #pragma unroll
            for (int j = 0; j < 8; j++) {
                int c = col0 + wn + j * 8 + gc;
                float2 f = *(const float2*)(F32 + (size_t)r * DD + c);
                float2 acc2 = __half22float2(*(__half2*)&acc[i][j][half]);
                float2 o;
                o.x = cw * (acc2.x * inv) + (1.0f - cw) * f.x;
                o.y = cw * (acc2.y * inv) + (1.0f - cw) * f.y;
                *(float2*)(O + (size_t)r * DD + c) = o;
            }
        }
    }
}

// ---------------------------------------------------------------------------
extern "C" void kernel_launch(void* const* d_in, const int* in_sizes, int n_in,
                              void* d_out, int out_size) {
    const float* final_f = (const float*)d_in[0];
    const float* mid_f   = (const float*)d_in[1];
    float* out = (float*)d_out;

    static int configured = 0;
    if (!configured) {
        cudaFuncSetAttribute(sim_mma, cudaFuncAttributeMaxDynamicSharedMemorySize,
                             SIM_SMEM);
        cudaFuncSetAttribute(out_mma, cudaFuncAttributeMaxDynamicSharedMemorySize,
                             OUT_SMEM);
        configured = 1;
    }

    prep_kernel<<<NORM_BLKS + TR_BLKS, 256>>>(mid_f, final_f);

    sim_mma<<<dim3(NPAIRS, 1, BATCH), 128, SIM_SMEM>>>();

    out_mma<<<dim3(DD / 128, NN / 128, BATCH), 128, OUT_SMEM>>>(final_f, out);
}

// round 17
// speedup vs baseline: 1.2337x; 1.0833x over previous
#include <cuda_runtime.h>
#include <cuda_bf16.h>
#include <cuda_fp16.h>
#include <cuda_fp8.h>
#include <stdint.h>
#include <stddef.h>
#include <math.h>

#define BATCH 8
#define NN 2048
#define DD 768
#define NTILE 16
#define NPAIRS (NTILE * (NTILE + 1) / 2)   // 136 upper-triangle tiles

// ---------------- device scratch (allocation-free rule) ----------------
__device__ __nv_bfloat16 g_midn[(size_t)BATCH * NN * DD];   // normalized mid (bf16)
__device__ unsigned char g_ftp8[(size_t)BATCH * DD * NN];   // final^T (e4m3), [d][n]
__device__ unsigned char g_expb[(size_t)BATCH * NN * NN];   // e4m3 exp(sim)
__device__ unsigned      g_confbits[BATCH * NN];            // ordered-uint row max
__device__ float         g_rowsumf[BATCH * NN];             // fp32 row sum of exp

__device__ __forceinline__ uint32_t s2u(const void* p) {
    return (uint32_t)__cvta_generic_to_shared(p);
}
__device__ __forceinline__ void cpa16(void* dst, const void* src) {
    asm volatile("cp.async.cg.shared.global [%0], [%1], 16;"
                 :: "r"(s2u(dst)), "l"(src));
}
#define CP_COMMIT() asm volatile("cp.async.commit_group;")
#define CP_WAIT(n)  asm volatile("cp.async.wait_group %0;" :: "n"(n))

// monotonic float<->uint for atomicMax
__device__ __forceinline__ unsigned fenc(float x) {
    unsigned b = __float_as_uint(x);
    return (b & 0x80000000u) ? ~b : (b | 0x80000000u);
}
__device__ __forceinline__ float fdec(unsigned e) {
    unsigned b = (e & 0x80000000u) ? (e ^ 0x80000000u) : ~e;
    return __uint_as_float(b);
}
__device__ __forceinline__ uint32_t pk2f8(float a, float b2) {
    return (uint32_t)__nv_cvt_float2_to_fp8x2(make_float2(a, b2),
                                              __NV_SATFINITE, __NV_E4M3);
}
__device__ __forceinline__ uint32_t pk4f8(float a, float b2, float c, float d) {
    return pk2f8(a, b2) | (pk2f8(c, d) << 16);
}

// swizzled byte offset for fp8 tiles: 128 rows x 64 bytes, 16B chunks
__device__ __forceinline__ int off8(int r, int c16) {
    return (r << 6) | ((((c16) ^ ((r >> 1) & 3)) & 3) << 4);
}
// swizzled index (halves) for bf16 tiles with 64-half (128B) rows, 8-half chunks
__device__ __forceinline__ int swW(int row, int kc) {
    return (row << 6) | (((kc ^ (row & 7)) & 7) << 3);
}

// ---------------------------------------------------------------------------
// Kernel 1 (merged prep):
//  blocks [0, NORM_BLKS): single-pass L2-normalize mid -> bf16, reset stats.
//  blocks [NORM_BLKS, +TR_BLKS): transpose final fp32 [n][d] -> e4m3 [d][n],
//  coalesced 128B writes (tile 128n x 32d staged in SMEM as t[d][n]).
// ---------------------------------------------------------------------------
#define NORM_BLKS (BATCH * NN)
#define TR_BX (DD / 32)                    // 24 d-tiles
#define TR_BY (NN / 128)                   // 16 n-tiles
#define TR_BLKS (TR_BX * TR_BY * BATCH)    // 3072

__global__ void prep_kernel(const float* __restrict__ mid,
                            const float* __restrict__ fin) {
    __shared__ float shmem[32 * 133];
    const int tid = threadIdx.x;
    if (blockIdx.x < NORM_BLKS) {
        const int row = blockIdx.x;
        if (tid == 0) {
            g_confbits[row] = fenc(-INFINITY);
            g_rowsumf[row] = 0.f;
        }
        const float* x = mid + (size_t)row * DD;
        __nv_bfloat16* y = g_midn + (size_t)row * DD;

        // single pass: 3 elements per thread held in registers
        const float v0 = x[tid];
        const float v1 = x[tid + 256];
        const float v2 = x[tid + 512];
        float s = v0 * v0 + v1 * v1 + v2 * v2;

        float* sh = shmem;
        #pragma unroll
        for (int o = 16; o > 0; o >>= 1) s += __shfl_xor_sync(0xffffffffu, s, o);
        const int w = tid >> 5, l = tid & 31;
        if (l == 0) sh[w] = s;
        __syncthreads();
        if (w == 0) {
            float v = (tid < 8) ? sh[tid] : 0.f;
            #pragma unroll
            for (int o = 4; o > 0; o >>= 1) v += __shfl_xor_sync(0xffffffffu, v, o);
            if (tid == 0) sh[0] = v;
        }
        __syncthreads();
        const float inv = 1.0f / fmaxf(sqrtf(sh[0]), 1e-12f);
        y[tid]       = __float2bfloat16(v0 * inv);
        y[tid + 256] = __float2bfloat16(v1 * inv);
        y[tid + 512] = __float2bfloat16(v2 * inv);
    } else {
        const int bid = blockIdx.x - NORM_BLKS;
        const int b = bid / (TR_BX * TR_BY);
        const int rem = bid - b * (TR_BX * TR_BY);
        const int d0 = (rem % TR_BX) * 32, n0 = (rem / TR_BX) * 128;
        const float* F = fin + (size_t)b * NN * DD;
        unsigned char* T = g_ftp8 + (size_t)b * DD * NN;
        float (*t)[133] = (float(*)[133])shmem;   // [d][n], stride 133 -> no bank conflicts on store

        // load 128 n-rows x 32 d each (warp reads 128B contiguous), store transposed
        #pragma unroll
        for (int i = 0; i < 16; i++) {
            const int idx = tid + 256 * i;
            const int r = idx >> 5, d = idx & 31;
            t[d][r] = F[(size_t)(n0 + r) * DD + d0 + d];
        }
        __syncthreads();

        // write: warp lane j emits packed fp8 word (4 n-values) -> 128B/warp coalesced
        const int j = tid & 31;
        #pragma unroll
        for (int i = 0; i < 4; i++) {
            const int d = (tid >> 5) + 8 * i;
            const uint32_t word = pk4f8(t[d][4 * j + 0], t[d][4 * j + 1],
                                        t[d][4 * j + 2], t[d][4 * j + 3]);
            *(uint32_t*)(T + (size_t)(d0 + d) * NN + n0 + 4 * j) = word;
        }
    }
}

// ---------------------------------------------------------------------------
// Kernel 2: sim GEMM (upper-triangle tiles, bf16 HMMA). 128x128 CTA tile,
// 4 warps (64x64 warp tile), k-chunk 64 halves (128B rows), 3-stage pipeline,
// fragment double-buffering. Epilogue: exp(sim) e4m3 + row-max atomics +
// fused partial row sums (atomicAdd).
// ---------------------------------------------------------------------------
#define KT_SIM (DD / 64)                   // 12 iterations
#define STG    8192                        // halves per stage tile (128x64)
#define SIM_SMEM (6 * STG * 2)             // 98304 B (>= T buffer 66048)

__global__ __launch_bounds__(128, 2) void sim_mma() {
    extern __shared__ char dsm[];
    __nv_bfloat16* As = (__nv_bfloat16*)dsm;          // [3][STG]
    __nv_bfloat16* Bs = As + 3 * STG;                 // [3][STG]
    float* T = (float*)dsm;                           // [128][129], reused

    int t = blockIdx.x, bi = 0, rem = NTILE;
    while (t >= rem) { t -= rem; rem--; bi++; }
    const int bj = bi + t;
    const int b = blockIdx.z;
    const int row0 = bi << 7, col0 = bj << 7;
    const bool diag = (bi == bj);
    const __nv_bfloat16* Ab = g_midn + (size_t)b * NN * DD;
    const __nv_bfloat16* Bbase = diag ? As : Bs;      // diag: B operand = A tile

    const int tid = threadIdx.x, lane = tid & 31, wid = tid >> 5;
    const int wm = (wid >> 1) << 6;    // 0, 64
    const int wn = (wid & 1) << 6;     // 0, 64

    float acc[4][8][4];
    #pragma unroll
    for (int i = 0; i < 4; i++)
        #pragma unroll
        for (int j = 0; j < 8; j++)
            #pragma unroll
            for (int k = 0; k < 4; k++) acc[i][j][k] = 0.f;

    // loader: 1024 16B-chunks per tile, 8 per thread per operand
    #define SIM_LOAD(kt, p_)                                                    \
        do {                                                                    \
            _Pragma("unroll")                                                   \
            for (int q = 0; q < 8; q++) {                                       \
                int ch = tid + 128 * q;                                         \
                int r = ch >> 3, c = ch & 7;                                    \
                int so = swW(r, c);                                             \
                cpa16(&As[(p_) * STG + so],                                     \
                      Ab + (size_t)(row0 + r) * DD + (kt) + c * 8);             \
                if (!diag)                                                      \
                    cpa16(&Bs[(p_) * STG + so],                                 \
                          Ab + (size_t)(col0 + r) * DD + (kt) + c * 8);         \
            }                                                                   \
        } while (0)

    uint32_t af[2][4][4], bf[2][8][2];

    #define SIM_FRAGS(ks, fb)                                                   \
        do {                                                                    \
            _Pragma("unroll")                                                   \
            for (int i = 0; i < 4; i++) {                                       \
                int row = wm + i * 16 + (lane & 15);                            \
                int kc  = (ks) * 2 + (lane >> 4);                               \
                uint32_t ad = s2u(&As[p * STG + swW(row, kc)]);                 \
                asm volatile("ldmatrix.sync.aligned.m8n8.x4.shared.b16 {%0,%1,%2,%3}, [%4];" \
                    : "=r"(af[fb][i][0]), "=r"(af[fb][i][1]),                   \
                      "=r"(af[fb][i][2]), "=r"(af[fb][i][3]) : "r"(ad));        \
            }                                                                   \
            _Pragma("unroll")                                                   \
            for (int j2 = 0; j2 < 4; j2++) {                                    \
                int row = wn + j2 * 16 + (lane & 7) + (((lane >> 4) & 1) << 3); \
                int kc  = (ks) * 2 + ((lane >> 3) & 1);                         \
                uint32_t bd = s2u(&Bbase[p * STG + swW(row, kc)]);              \
                asm volatile("ldmatrix.sync.aligned.m8n8.x4.shared.b16 {%0,%1,%2,%3}, [%4];" \
                    : "=r"(bf[fb][j2 * 2][0]), "=r"(bf[fb][j2 * 2][1]),         \
                      "=r"(bf[fb][j2 * 2 + 1][0]), "=r"(bf[fb][j2 * 2 + 1][1])  \
                    : "r"(bd));                                                 \
            }                                                                   \
        } while (0)

    SIM_LOAD(0, 0);
    CP_COMMIT();
    SIM_LOAD(64, 1);
    CP_COMMIT();

    int p = 0, pw = 2;
    for (int kti = 0; kti < KT_SIM; kti++) {
        CP_WAIT(1);
        __syncthreads();
        if (kti + 2 < KT_SIM) SIM_LOAD((kti + 2) * 64, pw);
        CP_COMMIT();

        SIM_FRAGS(0, 0);
        #pragma unroll
        for (int ks = 0; ks < 4; ks++) {
            if (ks + 1 < 4) SIM_FRAGS(ks + 1, (ks + 1) & 1);
            const int fb = ks & 1;
            #pragma unroll
            for (int i = 0; i < 4; i++)
                #pragma unroll
                for (int j = 0; j < 8; j++)
                    asm volatile(
                        "mma.sync.aligned.m16n8k16.row.col.f32.bf16.bf16.f32 "
                        "{%0,%1,%2,%3}, {%4,%5,%6,%7}, {%8,%9}, {%0,%1,%2,%3};"
                        : "+f"(acc[i][j][0]), "+f"(acc[i][j][1]),
                          "+f"(acc[i][j][2]), "+f"(acc[i][j][3])
                        : "r"(af[fb][i][0]), "r"(af[fb][i][1]),
                          "r"(af[fb][i][2]), "r"(af[fb][i][3]),
                          "r"(bf[fb][j][0]), "r"(bf[fb][j][1]));
        }
        p = (p == 2) ? 0 : p + 1;
        pw = (pw == 2) ? 0 : pw + 1;
    }
    __syncthreads();   // all warps done reading stages before T overwrites them

    // ---- stage fp32 tile (diag zeroed) in SMEM ----
    const int gr = lane >> 2, gc = (lane & 3) << 1;
    #pragma unroll
    for (int i = 0; i < 4; i++) {
        const int rl = wm + i * 16 + gr;
        #pragma unroll
        for (int j = 0; j < 8; j++) {
            const int cl = wn + j * 8 + gc;
            const int gofs = (row0 + rl) - (col0 + cl);
            T[rl * 129 + cl]           = (gofs == 0)  ? 0.f : acc[i][j][0];
            T[rl * 129 + cl + 1]       = (gofs == 1)  ? 0.f : acc[i][j][1];
            T[(rl + 8) * 129 + cl]     = (gofs == -8) ? 0.f : acc[i][j][2];
            T[(rl + 8) * 129 + cl + 1] = (gofs == -7) ? 0.f : acc[i][j][3];
        }
    }
    __syncthreads();

    // ---- row pass: exp(tile) -> e4m3, row-max + partial row-sum atomics ----
    {
        const int rr = tid;                 // one row per thread
        float mx = -INFINITY, sm = 0.f;
        uint32_t* dst = (uint32_t*)(g_expb + (size_t)b * NN * NN
                                    + (size_t)(row0 + rr) * NN + col0);
        #pragma unroll
        for (int c = 0; c < 128; c += 4) {
            float v0 = T[rr * 129 + c + 0];
            float v1 = T[rr * 129 + c + 1];
            float v2 = T[rr * 129 + c + 2];
            float v3 = T[rr * 129 + c + 3];
            mx = fmaxf(mx, fmaxf(fmaxf(v0, v1), fmaxf(v2, v3)));
            float e0 = __expf(v0), e1 = __expf(v1);
            float e2 = __expf(v2), e3 = __expf(v3);
            sm += (e0 + e1) + (e2 + e3);
            dst[c >> 2] = pk4f8(e0, e1, e2, e3);
        }
        atomicMax(&g_confbits[b * NN + row0 + rr], fenc(mx));
        atomicAdd(&g_rowsumf[b * NN + row0 + rr], sm);
    }

    // ---- col pass (mirror) for off-diagonal tiles ----
    if (!diag) {
        const int cc = tid;                 // one column per thread
        float mx = -INFINITY, sm = 0.f;
        uint32_t* dst = (uint32_t*)(g_expb + (size_t)b * NN * NN
                                    + (size_t)(col0 + cc) * NN + row0);
        #pragma unroll
        for (int r = 0; r < 128; r += 4) {
            float v0 = T[(r + 0) * 129 + cc];
            float v1 = T[(r + 1) * 129 + cc];
            float v2 = T[(r + 2) * 129 + cc];
            float v3 = T[(r + 3) * 129 + cc];
            mx = fmaxf(mx, fmaxf(fmaxf(v0, v1), fmaxf(v2, v3)));
            float e0 = __expf(v0), e1 = __expf(v1);
            float e2 = __expf(v2), e3 = __expf(v3);
            sm += (e0 + e1) + (e2 + e3);
            dst[r >> 2] = pk4f8(e0, e1, e2, e3);
        }
        atomicMax(&g_confbits[b * NN + col0 + cc], fenc(mx));
        atomicAdd(&g_rowsumf[b * NN + col0 + cc], sm);
    }
}

// ---------------------------------------------------------------------------
// Kernel 3: refined = (E @ F) * rinv ; out = cw*refined + (1-cw)*final.
// fp8 e4m3 QMMA m16n8k32, FP16 accumulators, single frag buffer,
// k-chunk 64 bytes, 3-stage pipeline. conf/rinv read in epilogue.
// ---------------------------------------------------------------------------
#define KT_OUT (NN / 64)                   // 32 iterations
#define STG8   8192                        // bytes per stage tile (128x64)
#define OUT_SMEM (6 * STG8)                // 49152

__global__ __launch_bounds__(128, 3) void out_mma(const float* __restrict__ fin,
                                                  float* __restrict__ out) {
    extern __shared__ char dsm[];
    unsigned char* Es = (unsigned char*)dsm;          // [3][STG8]
    unsigned char* Fs = Es + 3 * STG8;                // [3][STG8]
    const int b = blockIdx.z;
    const int row0 = blockIdx.y << 7;   // n rows
    const int col0 = blockIdx.x << 7;   // d cols
    const unsigned char* Eb = g_expb + (size_t)b * NN * NN;
    const unsigned char* Tb = g_ftp8 + (size_t)b * DD * NN;

    const int tid = threadIdx.x, lane = tid & 31, wid = tid >> 5;
    const int wm = (wid >> 1) << 6;
    const int wn = (wid & 1) << 6;

    // fp16 accumulators: 2 regs per mma tile (4 halves)
    uint32_t acc[4][8][2];
    #pragma unroll
    for (int i = 0; i < 4; i++)
        #pragma unroll
        for (int j = 0; j < 8; j++) {
            acc[i][j][0] = 0u;
            acc[i][j][1] = 0u;
        }

    // loader: 512 16B chunks per tile, 4 per thread per operand
    #define OUT_LOAD(kt, p_)                                                    \
        do {                                                                    \
            _Pragma("unroll")                                                   \
            for (int q = 0; q < 4; q++) {                                       \
                int ch = tid + 128 * q;                                         \
                int r = ch >> 2, c = ch & 3;                                    \
                int so = off8(r, c);                                            \
                cpa16(&Es[(p_) * STG8 + so],                                    \
                      Eb + (size_t)(row0 + r) * NN + (kt) + c * 16);            \
                cpa16(&Fs[(p_) * STG8 + so],                                    \
                      Tb + (size_t)(col0 + r) * NN + (kt) + c * 16);            \
            }                                                                   \
        } while (0)

    OUT_LOAD(0, 0);
    CP_COMMIT();
    OUT_LOAD(64, 1);
    CP_COMMIT();

    int p = 0, pw = 2;
    for (int kti = 0; kti < KT_OUT; kti++) {
        CP_WAIT(1);
        __syncthreads();
        if (kti + 2 < KT_OUT) OUT_LOAD((kti + 2) * 64, pw);
        CP_COMMIT();

        #pragma unroll
        for (int ks = 0; ks < 2; ks++) {
            uint32_t af[4][4];
            #pragma unroll
            for (int i = 0; i < 4; i++) {
                int row = wm + i * 16 + (lane & 15);
                int c16 = ks * 2 + (lane >> 4);
                uint32_t ad = s2u(&Es[p * STG8 + off8(row, c16)]);
                asm volatile("ldmatrix.sync.aligned.m8n8.x4.shared.b16 {%0,%1,%2,%3}, [%4];"
                    : "=r"(af[i][0]), "=r"(af[i][1]), "=r"(af[i][2]), "=r"(af[i][3])
                    : "r"(ad));
            }
            uint32_t bfr[8][2];
            #pragma unroll
            for (int j2 = 0; j2 < 4; j2++) {
                int row = wn + j2 * 16 + (lane & 7) + (((lane >> 4) & 1) << 3);
                int c16 = ks * 2 + ((lane >> 3) & 1);
                uint32_t bd = s2u(&Fs[p * STG8 + off8(row, c16)]);
                asm volatile("ldmatrix.sync.aligned.m8n8.x4.shared.b16 {%0,%1,%2,%3}, [%4];"
                    : "=r"(bfr[j2 * 2][0]), "=r"(bfr[j2 * 2][1]),
                      "=r"(bfr[j2 * 2 + 1][0]), "=r"(bfr[j2 * 2 + 1][1])
                    : "r"(bd));
            }
            #pragma unroll
            for (int i = 0; i < 4; i++)
                #pragma unroll
                for (int j = 0; j < 8; j++)
                    asm volatile(
                        "mma.sync.aligned.m16n8k32.row.col.f16.e4m3.e4m3.f16 "
                        "{%0,%1}, {%2,%3,%4,%5}, {%6,%7}, {%0,%1};"
                        : "+r"(acc[i][j][0]), "+r"(acc[i][j][1])
                        : "r"(af[i][0]), "r"(af[i][1]), "r"(af[i][2]), "r"(af[i][3]),
                          "r"(bfr[j][0]), "r"(bfr[j][1]));
        }
        p = (p == 2) ? 0 : p + 1;
        pw = (pw == 2) ? 0 : pw + 1;
    }

    const float* F32 = fin + (size_t)b * NN * DD;
    float* O = out + (size_t)b * NN * DD;
    const int gr = lane >> 2, gc = (lane & 3) << 1;
    #pragma unroll
    for (int i = 0; i < 4; i++) {
        #pragma unroll
        for (int half = 0; half < 2; half++) {
            int r = row0 + wm + i * 16 + gr + half * 8;
            const float cw  = fdec(g_confbits[b * NN + r]);
            const float inv = 1.0f / g_rowsumf[b * NN + r];
            #pragma unroll
            for (int j = 0; j < 8; j++) {
                int c = col0 + wn + j * 8 + gc;
                float2 f = *(const float2*)(F32 + (size_t)r * DD + c);
                float2 acc2 = __half22float2(*(__half2*)&acc[i][j][half]);
                float2 o;
                o.x = cw * (acc2.x * inv) + (1.0f - cw) * f.x;
                o.y = cw * (acc2.y * inv) + (1.0f - cw) * f.y;
                *(float2*)(O + (size_t)r * DD + c) = o;
            }
        }
    }
}

// ---------------------------------------------------------------------------
extern "C" void kernel_launch(void* const* d_in, const int* in_sizes, int n_in,
                              void* d_out, int out_size) {
    const float* final_f = (const float*)d_in[0];
    const float* mid_f   = (const float*)d_in[1];
    float* out = (float*)d_out;

    static int configured = 0;
    if (!configured) {
        cudaFuncSetAttribute(sim_mma, cudaFuncAttributeMaxDynamicSharedMemorySize,
                             SIM_SMEM);
        cudaFuncSetAttribute(out_mma, cudaFuncAttributeMaxDynamicSharedMemorySize,
                             OUT_SMEM);
        configured = 1;
    }

    prep_kernel<<<NORM_BLKS + TR_BLKS, 256>>>(mid_f, final_f);

    sim_mma<<<dim3(NPAIRS, 1, BATCH), 128, SIM_SMEM>>>();

    out_mma<<<dim3(DD / 128, NN / 128, BATCH), 128, OUT_SMEM>>>(final_f, out);
}